// round 9
// baseline (speedup 1.0000x reference)
#include <cuda_runtime.h>
#include <cuda_bf16.h>
#include <cstdint>

#define NN 20000
#define EE 320000
#define HH 280
#define GG 64
#define NFF 5
#define EFF 4
#define LL 3
#define ZZ 64
#define K_MSG 564   // 2H + EF
#define K_UPD 560   // 2H

// ---------------- scratch (static device globals; no runtime alloc) ----------------
__device__ float g_h[NN * HH];
__device__ float g_Y[EE * HH];
__device__ float g_agg[NN * HH];
__device__ float g_U[NN * HH];
__device__ float g_stats[2 * HH];
__device__ float g_scale[HH];
__device__ float g_shift[HH];
__device__ float g_pool[GG * HH];
__device__ float g_cnt[GG];
// pre-converted W images: per 64-k chunk, [288 n][64 k] bf16, 128B rows, SW128-swizzled
__device__ uint32_t g_wbh[9 * 9216];
__device__ uint32_t g_wbl[9 * 9216];

// ================= helpers =================
__device__ __forceinline__ uint32_t smem_u32(const void* p) {
    uint32_t a;
    asm("{ .reg .u64 t; cvta.to.shared.u64 t, %1; cvt.u32.u64 %0, t; }" : "=r"(a) : "l"(p));
    return a;
}
#define SWZ(o) ((o) ^ (((o) >> 3) & 0x70))

__device__ __forceinline__ void ldsm_x4(uint32_t* r, uint32_t addr) {
    asm volatile("ldmatrix.sync.aligned.m8n8.x4.shared.b16 {%0,%1,%2,%3}, [%4];"
                 : "=r"(r[0]), "=r"(r[1]), "=r"(r[2]), "=r"(r[3]) : "r"(addr));
}
__device__ __forceinline__ void mma_bf16(float* d, const uint32_t* a, uint32_t b0, uint32_t b1) {
    asm volatile("mma.sync.aligned.m16n8k16.row.col.f32.bf16.bf16.f32 "
                 "{%0,%1,%2,%3}, {%4,%5,%6,%7}, {%8,%9}, {%0,%1,%2,%3};"
                 : "+f"(d[0]), "+f"(d[1]), "+f"(d[2]), "+f"(d[3])
                 : "r"(a[0]), "r"(a[1]), "r"(a[2]), "r"(a[3]), "r"(b0), "r"(b1));
}
__device__ __forceinline__ void cp_async16(uint32_t dst, const void* src) {
    asm volatile("cp.async.cg.shared.global [%0], [%1], 16;" :: "r"(dst), "l"(src));
}
#define CP_COMMIT() asm volatile("cp.async.commit_group;" ::: "memory")
#define CP_WAIT0()  asm volatile("cp.async.wait_group 0;" ::: "memory")

// smem layout (bytes) for HMMA GEMMs — double-buffered A and B
#define SM_STAT  0         // 560 floats
#define SM_I0    2304      // 128 ints
#define SM_I1    2816
#define SM_SC    3328      // 280 floats (gemm2)
#define SM_SH    4480
#define SM_A     8192      // 2 bufs x (AH 16KB + AL 16KB) = 64KB  -> 8192 + buf*32768
#define SM_B     73728     // 2 bufs x (BH 36KB + BL 36KB) = 144KB -> 73728 + buf*73728
#define SM_TOT   221184    // 216KB

// ---------------- f32x2 helpers (node-GEMM path) ----------------
__device__ __forceinline__ uint64_t f32x2_fma(uint64_t a, uint64_t b, uint64_t c) {
    uint64_t d;
    asm("fma.rn.f32x2 %0, %1, %2, %3;" : "=l"(d) : "l"(a), "l"(b), "l"(c));
    return d;
}
__device__ __forceinline__ uint64_t f32x2_add(uint64_t a, uint64_t b) {
    uint64_t d;
    asm("add.rn.f32x2 %0, %1, %2;" : "=l"(d) : "l"(a), "l"(b));
    return d;
}
__device__ __forceinline__ uint64_t f32_rep2(float x) {
    uint64_t d;
    asm("mov.b64 %0, {%1, %1};" : "=l"(d) : "f"(x));
    return d;
}
__device__ __forceinline__ void f32x2_unpack(uint64_t v, float& lo, float& hi) {
    asm("mov.b64 {%0, %1}, %2;" : "=f"(lo), "=f"(hi) : "l"(v));
}

// ---------------- misc kernels ----------------
__global__ void zero4_kernel(float4* __restrict__ p, int n4) {
    int i = blockIdx.x * 256 + threadIdx.x;
    if (i < n4) p[i] = make_float4(0.f, 0.f, 0.f, 0.f);
}

__global__ void input_layer(const float* __restrict__ x, const float* __restrict__ Wi,
                            const float* __restrict__ bi, float* __restrict__ h) {
    int idx = blockIdx.x * 256 + threadIdx.x;
    if (idx >= NN * HH) return;
    int n = idx / HH;
    int c = idx - n * HH;
    float s = bi[c];
#pragma unroll
    for (int f = 0; f < NFF; f++) s = fmaf(x[n * NFF + f], Wi[f * HH + c], s);
    h[idx] = s;
}

// ---------------- W pre-conversion: fp32 [K,280] -> swizzled bf16 hi/lo chunk images ----
__global__ void conv_w(const float* __restrict__ W, int K, int nCh,
                       uint32_t* __restrict__ oh, uint32_t* __restrict__ ol) {
    int i = blockIdx.x * 256 + threadIdx.x;
    if (i >= nCh * 9216) return;
    int ch = i / 9216;
    int rem = i - ch * 9216;
    int kp = rem / 288;          // 0..31 (pair of k)
    int n = rem - kp * 288;      // 0..287
    int k0 = ch * 64 + 2 * kp;
    float v0 = (k0 < K && n < HH) ? W[(long)k0 * HH + n] : 0.f;
    float v1 = (k0 + 1 < K && n < HH) ? W[(long)(k0 + 1) * HH + n] : 0.f;
    __nv_bfloat162 hi = __floats2bfloat162_rn(v0, v1);
    __nv_bfloat162 lo = __floats2bfloat162_rn(v0 - __bfloat162float(hi.x),
                                              v1 - __bfloat162float(hi.y));
    uint32_t off = SWZ((uint32_t)(n * 128 + kp * 4));
    oh[ch * 9216 + (off >> 2)] = *reinterpret_cast<uint32_t*>(&hi);
    ol[ch * 9216 + (off >> 2)] = *reinterpret_cast<uint32_t*>(&lo);
}

// ============================================================================
// HMMA compute core: one 64-k chunk of 128x288 output, split-bf16.
// Product-major MMA order: same-accumulator MMAs separated by 4 independents.
// ============================================================================
__device__ __forceinline__ void hmma_chunk(uint32_t sb, int buf, int wm, int wn,
                                           int lane, float acc[2][18][4]) {
    const uint32_t abase = sb + SM_A + buf * 32768;
    const uint32_t bbase = sb + SM_B + buf * 73728;
#pragma unroll
    for (int ks = 0; ks < 4; ks++) {
        uint32_t ah[2][4], al[2][4];
#pragma unroll
        for (int mt = 0; mt < 2; mt++) {
            int row = wm * 32 + mt * 16 + (lane & 15);
            int koff = ks * 32 + ((lane >> 4) << 4);
            uint32_t o = SWZ((uint32_t)(row * 128 + koff));
            ldsm_x4(ah[mt], abase + o);
            ldsm_x4(al[mt], abase + 16384 + o);
        }
#pragma unroll
        for (int nt2 = 0; nt2 < 9; nt2++) {
            int n = wn * 144 + nt2 * 16 + ((lane >> 4) << 3) + (lane & 7);
            int koff = ks * 32 + ((lane >> 3) & 1) * 16;
            uint32_t o = SWZ((uint32_t)(n * 128 + koff));
            uint32_t bh[4], bl[4];
            ldsm_x4(bh, bbase + o);
            ldsm_x4(bl, bbase + 36864 + o);
            // product-major: hh (4), lh (4), hl (4)
#pragma unroll
            for (int mt = 0; mt < 2; mt++)
#pragma unroll
                for (int p = 0; p < 2; p++)
                    mma_bf16(acc[mt][nt2 * 2 + p], ah[mt], bh[2 * p], bh[2 * p + 1]);
#pragma unroll
            for (int mt = 0; mt < 2; mt++)
#pragma unroll
                for (int p = 0; p < 2; p++)
                    mma_bf16(acc[mt][nt2 * 2 + p], al[mt], bh[2 * p], bh[2 * p + 1]);
#pragma unroll
            for (int mt = 0; mt < 2; mt++)
#pragma unroll
                for (int p = 0; p < 2; p++)
                    mma_bf16(acc[mt][nt2 * 2 + p], ah[mt], bl[2 * p], bl[2 * p + 1]);
        }
    }
}

// Shared epilogue: bias + store + fused BN stats.
__device__ __forceinline__ void hmma_epilogue(float acc[2][18][4], long row0, int wm, int wn,
                                              int lane, const float* __restrict__ bias,
                                              float* __restrict__ Cout, float* sStat) {
    int rbase = wm * 32 + (lane >> 2);
    int cbase = wn * 144 + (lane & 3) * 2;
#pragma unroll
    for (int nt = 0; nt < 18; nt++) {
        int c = cbase + nt * 8;
        if (c < HH) {
            float b0 = bias[c], b1 = bias[c + 1];
            float s0 = 0.f, s1 = 0.f, q0 = 0.f, q1 = 0.f;
#pragma unroll
            for (int mt = 0; mt < 2; mt++) {
                float v0 = acc[mt][nt][0] + b0;
                float v1 = acc[mt][nt][1] + b1;
                float v2 = acc[mt][nt][2] + b0;
                float v3 = acc[mt][nt][3] + b1;
                long r1 = row0 + rbase + mt * 16;
                *reinterpret_cast<float2*>(Cout + r1 * HH + c) = make_float2(v0, v1);
                *reinterpret_cast<float2*>(Cout + (r1 + 8) * HH + c) = make_float2(v2, v3);
                s0 += v0 + v2; s1 += v1 + v3;
                q0 += v0 * v0 + v2 * v2;
                q1 += v1 * v1 + v3 * v3;
            }
            atomicAdd(&sStat[c], s0);
            atomicAdd(&sStat[c + 1], s1);
            atomicAdd(&sStat[HH + c], q0);
            atomicAdd(&sStat[HH + c + 1], q1);
        }
    }
}

// ============================================================================
// Edge GEMM1: Y[E,280] = cat(h[dst], h[src], ea) @ W1[564,280] + b  (HMMA, pipelined)
// ============================================================================
__global__ void __launch_bounds__(256)
gemm1_mma(const float* __restrict__ h, const int* __restrict__ idxD,
          const int* __restrict__ idxS, const float* __restrict__ ea,
          const uint32_t* __restrict__ wbh, const uint32_t* __restrict__ wbl,
          const float* __restrict__ bias, float* __restrict__ Cout) {
    extern __shared__ char sm[];
    uint32_t sb = smem_u32(sm);
    const int tid = threadIdx.x, wid = tid >> 5, lane = tid & 31;
    const int wm = wid >> 1, wn = wid & 1;
    const long row0 = (long)blockIdx.x * 128;
    int* sI0 = (int*)(sm + SM_I0);
    int* sI1 = (int*)(sm + SM_I1);
    float* sStat = (float*)(sm + SM_STAT);

    for (int i = tid; i < 2 * HH; i += 256) sStat[i] = 0.f;
    if (tid < 128) {
        sI0[tid] = idxD[row0 + tid];
        sI1[tid] = idxS[row0 + tid];
    }
    float acc[2][18][4];
#pragma unroll
    for (int mt = 0; mt < 2; mt++)
#pragma unroll
        for (int nt = 0; nt < 18; nt++)
#pragma unroll
            for (int j = 0; j < 4; j++) acc[mt][nt][j] = 0.f;
    __syncthreads();  // indices visible

    auto cpB = [&](int ch, int buf) {
        uint32_t dh = sb + SM_B + buf * 73728;
        const float4* s1 = (const float4*)(wbh + ch * 9216);
        const float4* s2 = (const float4*)(wbl + ch * 9216);
        for (int i = tid; i < 2304; i += 256) {
            cp_async16(dh + i * 16, s1 + i);
            cp_async16(dh + 36864 + i * 16, s2 + i);
        }
    };
    auto stageA = [&](int ch, int buf) {
        const int kbase = ch * 64;
        char* ab = sm + SM_A + buf * 32768;
        for (int i = tid; i < 4096; i += 256) {
            int r = i >> 5, kp = i & 31;
            int c = kbase + 2 * kp;
            float2 v = make_float2(0.f, 0.f);
            if (c < HH)            v = *(const float2*)(h + (long)sI0[r] * HH + c);
            else if (c < 2 * HH)   v = *(const float2*)(h + (long)sI1[r] * HH + (c - HH));
            else if (c < K_MSG)    v = *(const float2*)(ea + (row0 + r) * EFF + (c - 2 * HH));
            __nv_bfloat162 hi = __floats2bfloat162_rn(v.x, v.y);
            __nv_bfloat162 lo = __floats2bfloat162_rn(v.x - __bfloat162float(hi.x),
                                                      v.y - __bfloat162float(hi.y));
            uint32_t off = SWZ((uint32_t)(r * 128 + kp * 4));
            *(uint32_t*)(ab + off) = *reinterpret_cast<uint32_t*>(&hi);
            *(uint32_t*)(ab + 16384 + off) = *reinterpret_cast<uint32_t*>(&lo);
        }
    };

    cpB(0, 0);
    CP_COMMIT();
    stageA(0, 0);
    CP_WAIT0();
    __syncthreads();

    for (int ch = 0; ch < 9; ++ch) {
        const int buf = ch & 1;
        if (ch + 1 < 9) {
            cpB(ch + 1, buf ^ 1);
            CP_COMMIT();
            stageA(ch + 1, buf ^ 1);
        }
        hmma_chunk(sb, buf, wm, wn, lane, acc);
        if (ch + 1 < 9) CP_WAIT0();
        __syncthreads();
    }

    hmma_epilogue(acc, row0, wm, wn, lane, bias, Cout, sStat);
    __syncthreads();
    for (int i = tid; i < 2 * HH; i += 256) atomicAdd(&g_stats[i], sStat[i]);
}

// ============================================================================
// Edge GEMM2 (in place): C[E,280] = relu(bn(C)) @ W2[280,280] + b  (HMMA, pipelined)
// ============================================================================
__global__ void __launch_bounds__(256)
gemm2_mma(float* __restrict__ C,
          const uint32_t* __restrict__ wbh, const uint32_t* __restrict__ wbl,
          const float* __restrict__ bias) {
    extern __shared__ char sm[];
    uint32_t sb = smem_u32(sm);
    const int tid = threadIdx.x, wid = tid >> 5, lane = tid & 31;
    const int wm = wid >> 1, wn = wid & 1;
    const long row0 = (long)blockIdx.x * 128;
    float* sStat = (float*)(sm + SM_STAT);
    float* sSc = (float*)(sm + SM_SC);
    float* sSh = (float*)(sm + SM_SH);

    for (int i = tid; i < 2 * HH; i += 256) sStat[i] = 0.f;
    for (int i = tid; i < HH; i += 256) { sSc[i] = g_scale[i]; sSh[i] = g_shift[i]; }
    float acc[2][18][4];
#pragma unroll
    for (int mt = 0; mt < 2; mt++)
#pragma unroll
        for (int nt = 0; nt < 18; nt++)
#pragma unroll
            for (int j = 0; j < 4; j++) acc[mt][nt][j] = 0.f;
    __syncthreads();  // scale/shift visible

    auto cpB = [&](int ch, int buf) {
        uint32_t dh = sb + SM_B + buf * 73728;
        const float4* s1 = (const float4*)(wbh + ch * 9216);
        const float4* s2 = (const float4*)(wbl + ch * 9216);
        for (int i = tid; i < 2304; i += 256) {
            cp_async16(dh + i * 16, s1 + i);
            cp_async16(dh + 36864 + i * 16, s2 + i);
        }
    };
    auto stageA = [&](int ch, int buf) {
        const int kbase = ch * 64;
        char* ab = sm + SM_A + buf * 32768;
        for (int i = tid; i < 4096; i += 256) {
            int r = i >> 5, kp = i & 31;
            int c = kbase + 2 * kp;
            float2 v = make_float2(0.f, 0.f);
            if (c < HH) {
                float2 y = *(const float2*)(C + (row0 + r) * HH + c);
                v.x = fmaxf(fmaf(y.x, sSc[c], sSh[c]), 0.f);
                v.y = fmaxf(fmaf(y.y, sSc[c + 1], sSh[c + 1]), 0.f);
            }
            __nv_bfloat162 hi = __floats2bfloat162_rn(v.x, v.y);
            __nv_bfloat162 lo = __floats2bfloat162_rn(v.x - __bfloat162float(hi.x),
                                                      v.y - __bfloat162float(hi.y));
            uint32_t off = SWZ((uint32_t)(r * 128 + kp * 4));
            *(uint32_t*)(ab + off) = *reinterpret_cast<uint32_t*>(&hi);
            *(uint32_t*)(ab + 16384 + off) = *reinterpret_cast<uint32_t*>(&lo);
        }
    };

    cpB(0, 0);
    CP_COMMIT();
    stageA(0, 0);
    CP_WAIT0();
    __syncthreads();

    for (int ch = 0; ch < 5; ++ch) {
        const int buf = ch & 1;
        if (ch + 1 < 5) {
            cpB(ch + 1, buf ^ 1);
            CP_COMMIT();
            stageA(ch + 1, buf ^ 1);
        }
        hmma_chunk(sb, buf, wm, wn, lane, acc);
        if (ch + 1 < 5) CP_WAIT0();
        __syncthreads();
    }

    hmma_epilogue(acc, row0, wm, wn, lane, bias, C, sStat);
    __syncthreads();
    for (int i = tid; i < 2 * HH; i += 256) atomicAdd(&g_stats[i], sStat[i]);
}

// ============================================================================
// node GEMMs — proven f32x2 path (157 blocks)
// ============================================================================
__global__ __launch_bounds__(320, 1)
void gemm_cat(const float* __restrict__ A0, const float* __restrict__ A1,
              const float* __restrict__ W, const float* __restrict__ bias,
              float* __restrict__ C, int M, int K) {
    __shared__ __align__(16) float sA[8 * 128];
    __shared__ __align__(16) float sW[8 * HH];
    __shared__ float sStat[2 * HH];

    const int tid = threadIdx.x;
    const int row0 = blockIdx.x * 128;
    for (int i = tid; i < 2 * HH; i += 320) sStat[i] = 0.f;
    const int rg = tid / 10;
    const int cg = tid - rg * 10;
    const int colbase = cg * 28;

    uint64_t acc[56];
#pragma unroll
    for (int j = 0; j < 14; j++) {
        uint64_t b2 = *reinterpret_cast<const uint64_t*>(bias + colbase + 2 * j);
#pragma unroll
        for (int i = 0; i < 4; i++) acc[i * 14 + j] = b2;
    }
    const int nCh = (K + 7) >> 3;
    for (int ch = 0; ch < nCh; ++ch) {
        const int kbase = ch * 8;
        __syncthreads();
        if (tid < 256) {
            const int r = tid >> 1;
            const int kk = (tid & 1) * 4;
            int row = row0 + r;
            if (row >= M) row = M - 1;
            float4 v;
            if (kbase < HH) v = *reinterpret_cast<const float4*>(A0 + (long)row * HH + kbase + kk);
            else            v = *reinterpret_cast<const float4*>(A1 + (long)row * HH + (kbase - HH) + kk);
            sA[(kk + 0) * 128 + r] = v.x;
            sA[(kk + 1) * 128 + r] = v.y;
            sA[(kk + 2) * 128 + r] = v.z;
            sA[(kk + 3) * 128 + r] = v.w;
        }
        {
            const float* wsrc = W + (long)kbase * HH;
#pragma unroll
            for (int i = 0; i < 7; i++) {
                int id = tid + i * 320;
                sW[id] = wsrc[id];
            }
        }
        __syncthreads();
#pragma unroll
        for (int k = 0; k < 8; k++) {
            float4 a = *reinterpret_cast<const float4*>(sA + k * 128 + rg * 4);
            uint64_t a2[4];
            a2[0] = f32_rep2(a.x); a2[1] = f32_rep2(a.y);
            a2[2] = f32_rep2(a.z); a2[3] = f32_rep2(a.w);
            const ulonglong2* wp = reinterpret_cast<const ulonglong2*>(sW + k * HH + colbase);
            uint64_t w[14];
#pragma unroll
            for (int j = 0; j < 7; j++) { ulonglong2 u = wp[j]; w[2 * j] = u.x; w[2 * j + 1] = u.y; }
#pragma unroll
            for (int i = 0; i < 4; i++)
#pragma unroll
                for (int j = 0; j < 14; j++)
                    acc[i * 14 + j] = f32x2_fma(a2[i], w[j], acc[i * 14 + j]);
        }
    }
    uint64_t sum[14], sq[14];
#pragma unroll
    for (int j = 0; j < 14; j++) { sum[j] = 0ull; sq[j] = 0ull; }
#pragma unroll
    for (int i = 0; i < 4; i++) {
        int row = row0 + rg * 4 + i;
        if (row < M) {
            uint64_t* out = reinterpret_cast<uint64_t*>(C + (long)row * HH + colbase);
#pragma unroll
            for (int j = 0; j < 14; j++) {
                uint64_t v = acc[i * 14 + j];
                out[j] = v;
                sum[j] = f32x2_add(sum[j], v);
                sq[j] = f32x2_fma(v, v, sq[j]);
            }
        }
    }
#pragma unroll
    for (int j = 0; j < 14; j++) {
        float lo, hi;
        f32x2_unpack(sum[j], lo, hi);
        atomicAdd(&sStat[colbase + 2 * j], lo);
        atomicAdd(&sStat[colbase + 2 * j + 1], hi);
        f32x2_unpack(sq[j], lo, hi);
        atomicAdd(&sStat[HH + colbase + 2 * j], lo);
        atomicAdd(&sStat[HH + colbase + 2 * j + 1], hi);
    }
    __syncthreads();
    for (int i = tid; i < 2 * HH; i += 320) atomicAdd(&g_stats[i], sStat[i]);
}

__global__ __launch_bounds__(320, 1)
void gemm_inplace(float* __restrict__ C, const float* __restrict__ W,
                  const float* __restrict__ bias, int M) {
    __shared__ __align__(16) float sA[8 * 128];
    __shared__ __align__(16) float sW[8 * HH];
    __shared__ __align__(16) float sScale[HH];
    __shared__ __align__(16) float sShift[HH];
    __shared__ float sStat[2 * HH];

    const int tid = threadIdx.x;
    const int row0 = blockIdx.x * 128;
    for (int i = tid; i < 2 * HH; i += 320) sStat[i] = 0.f;
    if (tid < HH) { sScale[tid] = g_scale[tid]; sShift[tid] = g_shift[tid]; }
    const int rg = tid / 10;
    const int cg = tid - rg * 10;
    const int colbase = cg * 28;

    uint64_t acc[56];
#pragma unroll
    for (int j = 0; j < 14; j++) {
        uint64_t b2 = *reinterpret_cast<const uint64_t*>(bias + colbase + 2 * j);
#pragma unroll
        for (int i = 0; i < 4; i++) acc[i * 14 + j] = b2;
    }
    const int nCh = HH / 8;
    for (int ch = 0; ch < nCh; ++ch) {
        const int kbase = ch * 8;
        __syncthreads();
        if (tid < 256) {
            const int r = tid >> 1;
            const int kk = (tid & 1) * 4;
            int row = row0 + r;
            if (row >= M) row = M - 1;
            float4 v = *reinterpret_cast<const float4*>(C + (long)row * HH + kbase + kk);
            float4 s = *reinterpret_cast<const float4*>(sScale + kbase + kk);
            float4 t = *reinterpret_cast<const float4*>(sShift + kbase + kk);
            sA[(kk + 0) * 128 + r] = fmaxf(fmaf(v.x, s.x, t.x), 0.f);
            sA[(kk + 1) * 128 + r] = fmaxf(fmaf(v.y, s.y, t.y), 0.f);
            sA[(kk + 2) * 128 + r] = fmaxf(fmaf(v.z, s.z, t.z), 0.f);
            sA[(kk + 3) * 128 + r] = fmaxf(fmaf(v.w, s.w, t.w), 0.f);
        }
        {
            const float* wsrc = W + (long)kbase * HH;
#pragma unroll
            for (int i = 0; i < 7; i++) {
                int id = tid + i * 320;
                sW[id] = wsrc[id];
            }
        }
        __syncthreads();
#pragma unroll
        for (int k = 0; k < 8; k++) {
            float4 a = *reinterpret_cast<const float4*>(sA + k * 128 + rg * 4);
            uint64_t a2[4];
            a2[0] = f32_rep2(a.x); a2[1] = f32_rep2(a.y);
            a2[2] = f32_rep2(a.z); a2[3] = f32_rep2(a.w);
            const ulonglong2* wp = reinterpret_cast<const ulonglong2*>(sW + k * HH + colbase);
            uint64_t w[14];
#pragma unroll
            for (int j = 0; j < 7; j++) { ulonglong2 u = wp[j]; w[2 * j] = u.x; w[2 * j + 1] = u.y; }
#pragma unroll
            for (int i = 0; i < 4; i++)
#pragma unroll
                for (int j = 0; j < 14; j++)
                    acc[i * 14 + j] = f32x2_fma(a2[i], w[j], acc[i * 14 + j]);
        }
    }
    uint64_t sum[14], sq[14];
#pragma unroll
    for (int j = 0; j < 14; j++) { sum[j] = 0ull; sq[j] = 0ull; }
#pragma unroll
    for (int i = 0; i < 4; i++) {
        int row = row0 + rg * 4 + i;
        if (row < M) {
            uint64_t* out = reinterpret_cast<uint64_t*>(C + (long)row * HH + colbase);
#pragma unroll
            for (int j = 0; j < 14; j++) {
                uint64_t v = acc[i * 14 + j];
                out[j] = v;
                sum[j] = f32x2_add(sum[j], v);
                sq[j] = f32x2_fma(v, v, sq[j]);
            }
        }
    }
#pragma unroll
    for (int j = 0; j < 14; j++) {
        float lo, hi;
        f32x2_unpack(sum[j], lo, hi);
        atomicAdd(&sStat[colbase + 2 * j], lo);
        atomicAdd(&sStat[colbase + 2 * j + 1], hi);
        f32x2_unpack(sq[j], lo, hi);
        atomicAdd(&sStat[HH + colbase + 2 * j], lo);
        atomicAdd(&sStat[HH + colbase + 2 * j + 1], hi);
    }
    __syncthreads();
    for (int i = tid; i < 2 * HH; i += 320) atomicAdd(&g_stats[i], sStat[i]);
}

// ---------------- finalize BN stats -> scale/shift; self-zero ----------------
__global__ void finalize_stats(const float* __restrict__ g, const float* __restrict__ be,
                               float invM) {
    int c = threadIdx.x;
    if (c >= HH) return;
    float s = g_stats[c];
    float s2 = g_stats[HH + c];
    g_stats[c] = 0.f;
    g_stats[HH + c] = 0.f;
    float mean = s * invM;
    float var = s2 * invM - mean * mean;
    float rstd = rsqrtf(var + 1e-5f);
    float sc = g[c] * rstd;
    g_scale[c] = sc;
    g_shift[c] = fmaf(-mean, sc, be[c]);
}

// ---------------- scatter: agg[dst[e]] += relu(bn(Y[e])) ----------------
__global__ void scatter_bn_relu(const float* __restrict__ Y, const int* __restrict__ dst,
                                float* __restrict__ agg) {
    long i = (long)blockIdx.x * 256 + threadIdx.x;
    if (i >= (long)EE * (HH / 4)) return;
    int e = (int)(i / (HH / 4));
    int c = (int)(i - (long)e * (HH / 4)) * 4;
    float4 y = *reinterpret_cast<const float4*>(Y + (long)e * HH + c);
    float* p = agg + (long)dst[e] * HH + c;
    float v0 = fmaf(y.x, g_scale[c + 0], g_shift[c + 0]);
    float v1 = fmaf(y.y, g_scale[c + 1], g_shift[c + 1]);
    float v2 = fmaf(y.z, g_scale[c + 2], g_shift[c + 2]);
    float v3 = fmaf(y.w, g_scale[c + 3], g_shift[c + 3]);
    if (v0 > 0.f) atomicAdd(p + 0, v0);
    if (v1 > 0.f) atomicAdd(p + 1, v1);
    if (v2 > 0.f) atomicAdd(p + 2, v2);
    if (v3 > 0.f) atomicAdd(p + 3, v3);
}

// ---------------- residual: h += relu(bn(U)) ----------------
__global__ void residual_bn_relu(const float* __restrict__ U, float* __restrict__ h) {
    int i = blockIdx.x * 256 + threadIdx.x;
    if (i >= NN * HH / 4) return;
    int c = (i % (HH / 4)) * 4;
    float4 u = *reinterpret_cast<const float4*>(U + (long)i * 4);
    float4 hv = *reinterpret_cast<float4*>(h + (long)i * 4);
    hv.x += fmaxf(fmaf(u.x, g_scale[c + 0], g_shift[c + 0]), 0.f);
    hv.y += fmaxf(fmaf(u.y, g_scale[c + 1], g_shift[c + 1]), 0.f);
    hv.z += fmaxf(fmaf(u.z, g_scale[c + 2], g_shift[c + 2]), 0.f);
    hv.w += fmaxf(fmaf(u.w, g_scale[c + 3], g_shift[c + 3]), 0.f);
    *reinterpret_cast<float4*>(h + (long)i * 4) = hv;
}

// ---------------- pooling + head ----------------
__global__ void pool_accum(const float* __restrict__ h, const int* __restrict__ batch,
                           float* __restrict__ pool) {
    int i = blockIdx.x * 256 + threadIdx.x;
    if (i >= NN * HH / 4) return;
    int n = i / (HH / 4);
    int c = (i - n * (HH / 4)) * 4;
    float4 v = *reinterpret_cast<const float4*>(h + (long)i * 4);
    float* p = pool + (long)batch[n] * HH + c;
    atomicAdd(p + 0, v.x);
    atomicAdd(p + 1, v.y);
    atomicAdd(p + 2, v.z);
    atomicAdd(p + 3, v.w);
}

__global__ void pool_count(const int* __restrict__ batch, float* __restrict__ cnt) {
    int n = blockIdx.x * 256 + threadIdx.x;
    if (n < NN) atomicAdd(&cnt[batch[n]], 1.0f);
}

__global__ void head_kernel(const float* __restrict__ pool, const float* __restrict__ cnt,
                            const float* __restrict__ Wmu, const float* __restrict__ bmu,
                            float* __restrict__ out) {
    int gph = blockIdx.x;
    int z = threadIdx.x;
    float inv = 1.0f / fmaxf(cnt[gph], 1.0f);
    float s = bmu[z];
    for (int k = 0; k < HH; k++) s = fmaf(pool[gph * HH + k] * inv, Wmu[k * ZZ + z], s);
    out[gph * ZZ + z] = s;
}

// ---------------- host orchestration ----------------
extern "C" void kernel_launch(void* const* d_in, const int* in_sizes, int n_in,
                              void* d_out, int out_size) {
    const float *x, *edge_attr, *Wi, *bi, *Wm1, *bm1, *g1, *be1, *Wm2, *bm2, *g2, *be2;
    const float *Wu1, *bu1, *g3, *be3, *Wu2, *bu2, *g4, *be4, *Wmu, *bmu;
    const int *edge_index, *batch;

    if (in_sizes[2] == 2 * EE) {
        x = (const float*)d_in[0];   edge_attr = (const float*)d_in[1];
        edge_index = (const int*)d_in[2]; batch = (const int*)d_in[3];
        Wi = (const float*)d_in[4];  bi = (const float*)d_in[5];
        Wm1 = (const float*)d_in[6]; bm1 = (const float*)d_in[7];
        g1 = (const float*)d_in[8];  be1 = (const float*)d_in[9];
        Wm2 = (const float*)d_in[10]; bm2 = (const float*)d_in[11];
        g2 = (const float*)d_in[12]; be2 = (const float*)d_in[13];
        Wu1 = (const float*)d_in[14]; bu1 = (const float*)d_in[15];
        g3 = (const float*)d_in[16]; be3 = (const float*)d_in[17];
        Wu2 = (const float*)d_in[18]; bu2 = (const float*)d_in[19];
        g4 = (const float*)d_in[20]; be4 = (const float*)d_in[21];
        Wmu = (const float*)d_in[22]; bmu = (const float*)d_in[23];
    } else {
        x = (const float*)d_in[0];   edge_attr = (const float*)d_in[1];
        Wi = (const float*)d_in[2];  bi = (const float*)d_in[3];
        Wm1 = (const float*)d_in[4]; bm1 = (const float*)d_in[5];
        g1 = (const float*)d_in[6];  be1 = (const float*)d_in[7];
        Wm2 = (const float*)d_in[8]; bm2 = (const float*)d_in[9];
        g2 = (const float*)d_in[10]; be2 = (const float*)d_in[11];
        Wu1 = (const float*)d_in[12]; bu1 = (const float*)d_in[13];
        g3 = (const float*)d_in[14]; be3 = (const float*)d_in[15];
        Wu2 = (const float*)d_in[16]; bu2 = (const float*)d_in[17];
        g4 = (const float*)d_in[18]; be4 = (const float*)d_in[19];
        Wmu = (const float*)d_in[20]; bmu = (const float*)d_in[21];
        edge_index = (const int*)d_in[22]; batch = (const int*)d_in[23];
    }
    const int* src = edge_index;
    const int* dst = edge_index + EE;

    float *hbuf, *Ybuf, *aggbuf, *Ubuf, *poolbuf, *cntbuf, *statsbuf;
    uint32_t *wbh, *wbl;
    cudaGetSymbolAddress((void**)&hbuf, g_h);
    cudaGetSymbolAddress((void**)&Ybuf, g_Y);
    cudaGetSymbolAddress((void**)&aggbuf, g_agg);
    cudaGetSymbolAddress((void**)&Ubuf, g_U);
    cudaGetSymbolAddress((void**)&poolbuf, g_pool);
    cudaGetSymbolAddress((void**)&cntbuf, g_cnt);
    cudaGetSymbolAddress((void**)&statsbuf, g_stats);
    cudaGetSymbolAddress((void**)&wbh, g_wbh);
    cudaGetSymbolAddress((void**)&wbl, g_wbl);

    cudaFuncSetAttribute(gemm1_mma, cudaFuncAttributeMaxDynamicSharedMemorySize, SM_TOT);
    cudaFuncSetAttribute(gemm2_mma, cudaFuncAttributeMaxDynamicSharedMemorySize, SM_TOT);

    const int NH_BLKS = (NN * HH + 255) / 256;
    const int NH4_BLKS = (NN * HH / 4 + 255) / 256;
    const int MSG_BLKS = EE / 128;                    // 2500
    const int UPD_BLKS = (NN + 127) / 128;            // 157
    const long EH4 = (long)EE * (HH / 4);
    const int SC_BLKS = (int)((EH4 + 255) / 256);

    zero4_kernel<<<1, 256>>>((float4*)statsbuf, 2 * HH / 4);
    input_layer<<<NH_BLKS, 256>>>(x, Wi, bi, hbuf);

    for (int l = 0; l < LL; l++) {
        const float* wm1 = Wm1 + (long)l * K_MSG * HH;
        const float* wm2 = Wm2 + (long)l * HH * HH;
        const float* wu1 = Wu1 + (long)l * K_UPD * HH;
        const float* wu2 = Wu2 + (long)l * HH * HH;

        // ---- message MLP on edges (HMMA tensor cores) ----
        conv_w<<<(9 * 9216) / 256, 256>>>(wm1, K_MSG, 9, wbh, wbl);
        gemm1_mma<<<MSG_BLKS, 256, SM_TOT>>>(hbuf, dst, src, edge_attr,
                                             wbh, wbl, bm1 + l * HH, Ybuf);
        finalize_stats<<<1, 288>>>(g1 + l * HH, be1 + l * HH, 1.0f / EE);
        conv_w<<<(5 * 9216) / 256, 256>>>(wm2, HH, 5, wbh, wbl);
        gemm2_mma<<<MSG_BLKS, 256, SM_TOT>>>(Ybuf, wbh, wbl, bm2 + l * HH);
        finalize_stats<<<1, 288>>>(g2 + l * HH, be2 + l * HH, 1.0f / EE);

        // ---- aggregate ----
        zero4_kernel<<<NH4_BLKS, 256>>>((float4*)aggbuf, NN * HH / 4);
        scatter_bn_relu<<<SC_BLKS, 256>>>(Ybuf, dst, aggbuf);

        // ---- update MLP on nodes (f32x2 path) ----
        gemm_cat<<<UPD_BLKS, 320>>>(hbuf, aggbuf, wu1, bu1 + l * HH, Ubuf, NN, K_UPD);
        finalize_stats<<<1, 288>>>(g3 + l * HH, be3 + l * HH, 1.0f / NN);
        gemm_inplace<<<UPD_BLKS, 320>>>(Ubuf, wu2, bu2 + l * HH, NN);
        finalize_stats<<<1, 288>>>(g4 + l * HH, be4 + l * HH, 1.0f / NN);
        residual_bn_relu<<<NH4_BLKS, 256>>>(Ubuf, hbuf);
    }

    zero4_kernel<<<(GG * HH / 4 + 255) / 256, 256>>>((float4*)poolbuf, GG * HH / 4);
    zero4_kernel<<<1, 256>>>((float4*)cntbuf, GG / 4);
    pool_accum<<<NH4_BLKS, 256>>>(hbuf, batch, poolbuf);
    pool_count<<<(NN + 255) / 256, 256>>>(batch, cntbuf);
    head_kernel<<<GG, ZZ>>>(poolbuf, cntbuf, Wmu, bmu, (float*)d_out);
}

// round 10
// speedup vs baseline: 1.1781x; 1.1781x over previous
#include <cuda_runtime.h>
#include <cuda_fp16.h>
#include <cstdint>

#define NN 20000
#define EE 320000
#define HH 280
#define GG 64
#define NFF 5
#define EFF 4
#define LL 3
#define ZZ 64
#define K_MSG 564   // 2H + EF
#define K_UPD 560   // 2H

// ---------------- scratch (static device globals; no runtime alloc) ----------------
__device__ float g_h[NN * HH];
__device__ float g_Y[EE * HH];
__device__ float g_agg[NN * HH];
__device__ float g_U[NN * HH];
__device__ float g_stats[2 * HH];
__device__ float g_scale[HH];
__device__ float g_shift[HH];
__device__ float g_pool[GG * HH];
__device__ float g_cnt[GG];
// pre-converted W image: per 64-k chunk, [288 n][64 k] fp16, 128B rows, SW128-swizzled
__device__ uint32_t g_wb[9 * 9216];

// ================= helpers =================
__device__ __forceinline__ uint32_t smem_u32(const void* p) {
    uint32_t a;
    asm("{ .reg .u64 t; cvta.to.shared.u64 t, %1; cvt.u32.u64 %0, t; }" : "=r"(a) : "l"(p));
    return a;
}
#define SWZ(o) ((o) ^ (((o) >> 3) & 0x70))

__device__ __forceinline__ void ldsm_x4(uint32_t* r, uint32_t addr) {
    asm volatile("ldmatrix.sync.aligned.m8n8.x4.shared.b16 {%0,%1,%2,%3}, [%4];"
                 : "=r"(r[0]), "=r"(r[1]), "=r"(r[2]), "=r"(r[3]) : "r"(addr));
}
__device__ __forceinline__ void mma_f16(float* d, const uint32_t* a, uint32_t b0, uint32_t b1) {
    asm volatile("mma.sync.aligned.m16n8k16.row.col.f32.f16.f16.f32 "
                 "{%0,%1,%2,%3}, {%4,%5,%6,%7}, {%8,%9}, {%0,%1,%2,%3};"
                 : "+f"(d[0]), "+f"(d[1]), "+f"(d[2]), "+f"(d[3])
                 : "r"(a[0]), "r"(a[1]), "r"(a[2]), "r"(a[3]), "r"(b0), "r"(b1));
}

// smem layout (bytes) for HMMA GEMMs (single-buffered — pipelining measured neutral/negative)
#define SM_STAT  0         // 560 floats
#define SM_I0    2304      // 128 ints
#define SM_I1    2816
#define SM_SC    3328      // 280 floats (gemm2)
#define SM_SH    4480
#define SM_AH    8192      // 128x64 fp16 swizzled (16KB)
#define SM_AL    24576     // 16KB
#define SM_BH    40960     // 288x64 fp16 swizzled (36KB)
#define SM_TOT   78848

// ---------------- f32x2 helpers (node-GEMM path) ----------------
__device__ __forceinline__ uint64_t f32x2_fma(uint64_t a, uint64_t b, uint64_t c) {
    uint64_t d;
    asm("fma.rn.f32x2 %0, %1, %2, %3;" : "=l"(d) : "l"(a), "l"(b), "l"(c));
    return d;
}
__device__ __forceinline__ uint64_t f32x2_add(uint64_t a, uint64_t b) {
    uint64_t d;
    asm("add.rn.f32x2 %0, %1, %2;" : "=l"(d) : "l"(a), "l"(b));
    return d;
}
__device__ __forceinline__ uint64_t f32_rep2(float x) {
    uint64_t d;
    asm("mov.b64 %0, {%1, %1};" : "=l"(d) : "f"(x));
    return d;
}
__device__ __forceinline__ void f32x2_unpack(uint64_t v, float& lo, float& hi) {
    asm("mov.b64 {%0, %1}, %2;" : "=f"(lo), "=f"(hi) : "l"(v));
}

// ---------------- misc kernels ----------------
__global__ void zero4_kernel(float4* __restrict__ p, int n4) {
    int i = blockIdx.x * 256 + threadIdx.x;
    if (i < n4) p[i] = make_float4(0.f, 0.f, 0.f, 0.f);
}

__global__ void input_layer(const float* __restrict__ x, const float* __restrict__ Wi,
                            const float* __restrict__ bi, float* __restrict__ h) {
    int idx = blockIdx.x * 256 + threadIdx.x;
    if (idx >= NN * HH) return;
    int n = idx / HH;
    int c = idx - n * HH;
    float s = bi[c];
#pragma unroll
    for (int f = 0; f < NFF; f++) s = fmaf(x[n * NFF + f], Wi[f * HH + c], s);
    h[idx] = s;
}

// ---------------- W pre-conversion: fp32 [K,280] -> swizzled fp16 chunk image ----
__global__ void conv_w(const float* __restrict__ W, int K, int nCh,
                       uint32_t* __restrict__ ob) {
    int i = blockIdx.x * 256 + threadIdx.x;
    if (i >= nCh * 9216) return;
    int ch = i / 9216;
    int rem = i - ch * 9216;
    int kp = rem / 288;          // 0..31 (pair of k)
    int n = rem - kp * 288;      // 0..287
    int k0 = ch * 64 + 2 * kp;
    float v0 = (k0 < K && n < HH) ? W[(long)k0 * HH + n] : 0.f;
    float v1 = (k0 + 1 < K && n < HH) ? W[(long)(k0 + 1) * HH + n] : 0.f;
    __half2 hv = __floats2half2_rn(v0, v1);
    uint32_t off = SWZ((uint32_t)(n * 128 + kp * 4));
    ob[ch * 9216 + (off >> 2)] = *reinterpret_cast<uint32_t*>(&hv);
}

// ============================================================================
// HMMA compute core: one 64-k chunk of 128x288 output, fp16 2-product split
// (A_hi*B + A_lo*B). n-tiles processed in pairs -> accumulator reuse distance 8.
// ============================================================================
__device__ __forceinline__ void hmma_chunk(uint32_t sb, int wm, int wn,
                                           int lane, float acc[2][18][4]) {
    const uint32_t abase = sb + SM_AH;
    const uint32_t bbase = sb + SM_BH;
#pragma unroll
    for (int ks = 0; ks < 4; ks++) {
        uint32_t ah[2][4], al[2][4];
#pragma unroll
        for (int mt = 0; mt < 2; mt++) {
            int row = wm * 32 + mt * 16 + (lane & 15);
            int koff = ks * 32 + ((lane >> 4) << 4);
            uint32_t o = SWZ((uint32_t)(row * 128 + koff));
            ldsm_x4(ah[mt], abase + o);
            ldsm_x4(al[mt], abase + 16384 + o);
        }
        int bkoff = ks * 32 + ((lane >> 3) & 1) * 16;
        int bn0 = wn * 144 + ((lane >> 4) << 3) + (lane & 7);
#pragma unroll
        for (int g = 0; g < 5; g++) {
            const int nta = 2 * g, ntb = 2 * g + 1;
            uint32_t ba[4], bb[4];
            ldsm_x4(ba, bbase + SWZ((uint32_t)((bn0 + nta * 16) * 128 + bkoff)));
            if (g < 4) ldsm_x4(bb, bbase + SWZ((uint32_t)((bn0 + ntb * 16) * 128 + bkoff)));
            // hi products for both groups (8 independent MMAs)
#pragma unroll
            for (int mt = 0; mt < 2; mt++)
#pragma unroll
                for (int p = 0; p < 2; p++)
                    mma_f16(acc[mt][nta * 2 + p], ah[mt], ba[2 * p], ba[2 * p + 1]);
            if (g < 4) {
#pragma unroll
                for (int mt = 0; mt < 2; mt++)
#pragma unroll
                    for (int p = 0; p < 2; p++)
                        mma_f16(acc[mt][ntb * 2 + p], ah[mt], bb[2 * p], bb[2 * p + 1]);
            }
            // lo products (reuse distance 8 from the hi writes)
#pragma unroll
            for (int mt = 0; mt < 2; mt++)
#pragma unroll
                for (int p = 0; p < 2; p++)
                    mma_f16(acc[mt][nta * 2 + p], al[mt], ba[2 * p], ba[2 * p + 1]);
            if (g < 4) {
#pragma unroll
                for (int mt = 0; mt < 2; mt++)
#pragma unroll
                    for (int p = 0; p < 2; p++)
                        mma_f16(acc[mt][ntb * 2 + p], al[mt], bb[2 * p], bb[2 * p + 1]);
            }
        }
    }
}

// Shared epilogue: bias + store + fused BN stats.
__device__ __forceinline__ void hmma_epilogue(float acc[2][18][4], long row0, int wm, int wn,
                                              int lane, const float* __restrict__ bias,
                                              float* __restrict__ Cout, float* sStat) {
    int rbase = wm * 32 + (lane >> 2);
    int cbase = wn * 144 + (lane & 3) * 2;
#pragma unroll
    for (int nt = 0; nt < 18; nt++) {
        int c = cbase + nt * 8;
        if (c < HH) {
            float b0 = bias[c], b1 = bias[c + 1];
            float s0 = 0.f, s1 = 0.f, q0 = 0.f, q1 = 0.f;
#pragma unroll
            for (int mt = 0; mt < 2; mt++) {
                float v0 = acc[mt][nt][0] + b0;
                float v1 = acc[mt][nt][1] + b1;
                float v2 = acc[mt][nt][2] + b0;
                float v3 = acc[mt][nt][3] + b1;
                long r1 = row0 + rbase + mt * 16;
                *reinterpret_cast<float2*>(Cout + r1 * HH + c) = make_float2(v0, v1);
                *reinterpret_cast<float2*>(Cout + (r1 + 8) * HH + c) = make_float2(v2, v3);
                s0 += v0 + v2; s1 += v1 + v3;
                q0 += v0 * v0 + v2 * v2;
                q1 += v1 * v1 + v3 * v3;
            }
            atomicAdd(&sStat[c], s0);
            atomicAdd(&sStat[c + 1], s1);
            atomicAdd(&sStat[HH + c], q0);
            atomicAdd(&sStat[HH + c + 1], q1);
        }
    }
}

// ============================================================================
// Edge GEMM1: Y[E,280] = cat(h[dst], h[src], ea) @ W1[564,280] + b  (HMMA fp16)
// ============================================================================
__global__ void __launch_bounds__(256)
gemm1_mma(const float* __restrict__ h, const int* __restrict__ idxD,
          const int* __restrict__ idxS, const float* __restrict__ ea,
          const uint32_t* __restrict__ wb,
          const float* __restrict__ bias, float* __restrict__ Cout) {
    extern __shared__ char sm[];
    uint32_t sb = smem_u32(sm);
    const int tid = threadIdx.x, wid = tid >> 5, lane = tid & 31;
    const int wm = wid >> 1, wn = wid & 1;
    const long row0 = (long)blockIdx.x * 128;
    int* sI0 = (int*)(sm + SM_I0);
    int* sI1 = (int*)(sm + SM_I1);
    float* sStat = (float*)(sm + SM_STAT);

    for (int i = tid; i < 2 * HH; i += 256) sStat[i] = 0.f;
    if (tid < 128) {
        sI0[tid] = idxD[row0 + tid];
        sI1[tid] = idxS[row0 + tid];
    }
    float acc[2][18][4];
#pragma unroll
    for (int mt = 0; mt < 2; mt++)
#pragma unroll
        for (int nt = 0; nt < 18; nt++)
#pragma unroll
            for (int j = 0; j < 4; j++) acc[mt][nt][j] = 0.f;
    __syncthreads();

    for (int ch = 0; ch < 9; ++ch) {
        if (ch) __syncthreads();
        const int kbase = ch * 64;
        // ---- stage A (gathered, fp32 -> hi/lo fp16, swizzled) ----
        for (int i = tid; i < 4096; i += 256) {
            int r = i >> 5, kp = i & 31;
            int c = kbase + 2 * kp;
            float2 v = make_float2(0.f, 0.f);
            if (c < HH)            v = *(const float2*)(h + (long)sI0[r] * HH + c);
            else if (c < 2 * HH)   v = *(const float2*)(h + (long)sI1[r] * HH + (c - HH));
            else if (c < K_MSG)    v = *(const float2*)(ea + (row0 + r) * EFF + (c - 2 * HH));
            __half2 hv = __floats2half2_rn(v.x, v.y);
            float2 hf = __half22float2(hv);
            __half2 lv = __floats2half2_rn(v.x - hf.x, v.y - hf.y);
            uint32_t off = SWZ((uint32_t)(r * 128 + kp * 4));
            *(uint32_t*)(sm + SM_AH + off) = *reinterpret_cast<uint32_t*>(&hv);
            *(uint32_t*)(sm + SM_AL + off) = *reinterpret_cast<uint32_t*>(&lv);
        }
        // ---- stage B (float4 copy of pre-swizzled fp16 image) ----
        {
            const float4* s1 = (const float4*)(wb + ch * 9216);
            float4* d1 = (float4*)(sm + SM_BH);
            for (int i = tid; i < 2304; i += 256) d1[i] = s1[i];
        }
        __syncthreads();
        hmma_chunk(sb, wm, wn, lane, acc);
    }

    hmma_epilogue(acc, row0, wm, wn, lane, bias, Cout, sStat);
    __syncthreads();
    for (int i = tid; i < 2 * HH; i += 256) atomicAdd(&g_stats[i], sStat[i]);
}

// ============================================================================
// Edge GEMM2 (in place): C[E,280] = relu(bn(C)) @ W2[280,280] + b  (HMMA fp16)
// ============================================================================
__global__ void __launch_bounds__(256)
gemm2_mma(float* __restrict__ C, const uint32_t* __restrict__ wb,
          const float* __restrict__ bias) {
    extern __shared__ char sm[];
    uint32_t sb = smem_u32(sm);
    const int tid = threadIdx.x, wid = tid >> 5, lane = tid & 31;
    const int wm = wid >> 1, wn = wid & 1;
    const long row0 = (long)blockIdx.x * 128;
    float* sStat = (float*)(sm + SM_STAT);
    float* sSc = (float*)(sm + SM_SC);
    float* sSh = (float*)(sm + SM_SH);

    for (int i = tid; i < 2 * HH; i += 256) sStat[i] = 0.f;
    for (int i = tid; i < HH; i += 256) { sSc[i] = g_scale[i]; sSh[i] = g_shift[i]; }
    float acc[2][18][4];
#pragma unroll
    for (int mt = 0; mt < 2; mt++)
#pragma unroll
        for (int nt = 0; nt < 18; nt++)
#pragma unroll
            for (int j = 0; j < 4; j++) acc[mt][nt][j] = 0.f;
    __syncthreads();

    for (int ch = 0; ch < 5; ++ch) {
        if (ch) __syncthreads();
        const int kbase = ch * 64;
        for (int i = tid; i < 4096; i += 256) {
            int r = i >> 5, kp = i & 31;
            int c = kbase + 2 * kp;
            float2 v = make_float2(0.f, 0.f);
            if (c < HH) {
                float2 y = *(const float2*)(C + (row0 + r) * HH + c);
                v.x = fmaxf(fmaf(y.x, sSc[c], sSh[c]), 0.f);
                v.y = fmaxf(fmaf(y.y, sSc[c + 1], sSh[c + 1]), 0.f);
            }
            __half2 hv = __floats2half2_rn(v.x, v.y);
            float2 hf = __half22float2(hv);
            __half2 lv = __floats2half2_rn(v.x - hf.x, v.y - hf.y);
            uint32_t off = SWZ((uint32_t)(r * 128 + kp * 4));
            *(uint32_t*)(sm + SM_AH + off) = *reinterpret_cast<uint32_t*>(&hv);
            *(uint32_t*)(sm + SM_AL + off) = *reinterpret_cast<uint32_t*>(&lv);
        }
        {
            const float4* s1 = (const float4*)(wb + ch * 9216);
            float4* d1 = (float4*)(sm + SM_BH);
            for (int i = tid; i < 2304; i += 256) d1[i] = s1[i];
        }
        __syncthreads();
        hmma_chunk(sb, wm, wn, lane, acc);
    }

    hmma_epilogue(acc, row0, wm, wn, lane, bias, C, sStat);
    __syncthreads();
    for (int i = tid; i < 2 * HH; i += 256) atomicAdd(&g_stats[i], sStat[i]);
}

// ============================================================================
// node GEMMs — proven f32x2 path (157 blocks)
// ============================================================================
__global__ __launch_bounds__(320, 1)
void gemm_cat(const float* __restrict__ A0, const float* __restrict__ A1,
              const float* __restrict__ W, const float* __restrict__ bias,
              float* __restrict__ C, int M, int K) {
    __shared__ __align__(16) float sA[8 * 128];
    __shared__ __align__(16) float sW[8 * HH];
    __shared__ float sStat[2 * HH];

    const int tid = threadIdx.x;
    const int row0 = blockIdx.x * 128;
    for (int i = tid; i < 2 * HH; i += 320) sStat[i] = 0.f;
    const int rg = tid / 10;
    const int cg = tid - rg * 10;
    const int colbase = cg * 28;

    uint64_t acc[56];
#pragma unroll
    for (int j = 0; j < 14; j++) {
        uint64_t b2 = *reinterpret_cast<const uint64_t*>(bias + colbase + 2 * j);
#pragma unroll
        for (int i = 0; i < 4; i++) acc[i * 14 + j] = b2;
    }
    const int nCh = (K + 7) >> 3;
    for (int ch = 0; ch < nCh; ++ch) {
        const int kbase = ch * 8;
        __syncthreads();
        if (tid < 256) {
            const int r = tid >> 1;
            const int kk = (tid & 1) * 4;
            int row = row0 + r;
            if (row >= M) row = M - 1;
            float4 v;
            if (kbase < HH) v = *reinterpret_cast<const float4*>(A0 + (long)row * HH + kbase + kk);
            else            v = *reinterpret_cast<const float4*>(A1 + (long)row * HH + (kbase - HH) + kk);
            sA[(kk + 0) * 128 + r] = v.x;
            sA[(kk + 1) * 128 + r] = v.y;
            sA[(kk + 2) * 128 + r] = v.z;
            sA[(kk + 3) * 128 + r] = v.w;
        }
        {
            const float* wsrc = W + (long)kbase * HH;
#pragma unroll
            for (int i = 0; i < 7; i++) {
                int id = tid + i * 320;
                sW[id] = wsrc[id];
            }
        }
        __syncthreads();
#pragma unroll
        for (int k = 0; k < 8; k++) {
            float4 a = *reinterpret_cast<const float4*>(sA + k * 128 + rg * 4);
            uint64_t a2[4];
            a2[0] = f32_rep2(a.x); a2[1] = f32_rep2(a.y);
            a2[2] = f32_rep2(a.z); a2[3] = f32_rep2(a.w);
            const ulonglong2* wp = reinterpret_cast<const ulonglong2*>(sW + k * HH + colbase);
            uint64_t w[14];
#pragma unroll
            for (int j = 0; j < 7; j++) { ulonglong2 u = wp[j]; w[2 * j] = u.x; w[2 * j + 1] = u.y; }
#pragma unroll
            for (int i = 0; i < 4; i++)
#pragma unroll
                for (int j = 0; j < 14; j++)
                    acc[i * 14 + j] = f32x2_fma(a2[i], w[j], acc[i * 14 + j]);
        }
    }
    uint64_t sum[14], sq[14];
#pragma unroll
    for (int j = 0; j < 14; j++) { sum[j] = 0ull; sq[j] = 0ull; }
#pragma unroll
    for (int i = 0; i < 4; i++) {
        int row = row0 + rg * 4 + i;
        if (row < M) {
            uint64_t* out = reinterpret_cast<uint64_t*>(C + (long)row * HH + colbase);
#pragma unroll
            for (int j = 0; j < 14; j++) {
                uint64_t v = acc[i * 14 + j];
                out[j] = v;
                sum[j] = f32x2_add(sum[j], v);
                sq[j] = f32x2_fma(v, v, sq[j]);
            }
        }
    }
#pragma unroll
    for (int j = 0; j < 14; j++) {
        float lo, hi;
        f32x2_unpack(sum[j], lo, hi);
        atomicAdd(&sStat[colbase + 2 * j], lo);
        atomicAdd(&sStat[colbase + 2 * j + 1], hi);
        f32x2_unpack(sq[j], lo, hi);
        atomicAdd(&sStat[HH + colbase + 2 * j], lo);
        atomicAdd(&sStat[HH + colbase + 2 * j + 1], hi);
    }
    __syncthreads();
    for (int i = tid; i < 2 * HH; i += 320) atomicAdd(&g_stats[i], sStat[i]);
}

__global__ __launch_bounds__(320, 1)
void gemm_inplace(float* __restrict__ C, const float* __restrict__ W,
                  const float* __restrict__ bias, int M) {
    __shared__ __align__(16) float sA[8 * 128];
    __shared__ __align__(16) float sW[8 * HH];
    __shared__ __align__(16) float sScale[HH];
    __shared__ __align__(16) float sShift[HH];
    __shared__ float sStat[2 * HH];

    const int tid = threadIdx.x;
    const int row0 = blockIdx.x * 128;
    for (int i = tid; i < 2 * HH; i += 320) sStat[i] = 0.f;
    if (tid < HH) { sScale[tid] = g_scale[tid]; sShift[tid] = g_shift[tid]; }
    const int rg = tid / 10;
    const int cg = tid - rg * 10;
    const int colbase = cg * 28;

    uint64_t acc[56];
#pragma unroll
    for (int j = 0; j < 14; j++) {
        uint64_t b2 = *reinterpret_cast<const uint64_t*>(bias + colbase + 2 * j);
#pragma unroll
        for (int i = 0; i < 4; i++) acc[i * 14 + j] = b2;
    }
    const int nCh = HH / 8;
    for (int ch = 0; ch < nCh; ++ch) {
        const int kbase = ch * 8;
        __syncthreads();
        if (tid < 256) {
            const int r = tid >> 1;
            const int kk = (tid & 1) * 4;
            int row = row0 + r;
            if (row >= M) row = M - 1;
            float4 v = *reinterpret_cast<const float4*>(C + (long)row * HH + kbase + kk);
            float4 s = *reinterpret_cast<const float4*>(sScale + kbase + kk);
            float4 t = *reinterpret_cast<const float4*>(sShift + kbase + kk);
            sA[(kk + 0) * 128 + r] = fmaxf(fmaf(v.x, s.x, t.x), 0.f);
            sA[(kk + 1) * 128 + r] = fmaxf(fmaf(v.y, s.y, t.y), 0.f);
            sA[(kk + 2) * 128 + r] = fmaxf(fmaf(v.z, s.z, t.z), 0.f);
            sA[(kk + 3) * 128 + r] = fmaxf(fmaf(v.w, s.w, t.w), 0.f);
        }
        {
            const float* wsrc = W + (long)kbase * HH;
#pragma unroll
            for (int i = 0; i < 7; i++) {
                int id = tid + i * 320;
                sW[id] = wsrc[id];
            }
        }
        __syncthreads();
#pragma unroll
        for (int k = 0; k < 8; k++) {
            float4 a = *reinterpret_cast<const float4*>(sA + k * 128 + rg * 4);
            uint64_t a2[4];
            a2[0] = f32_rep2(a.x); a2[1] = f32_rep2(a.y);
            a2[2] = f32_rep2(a.z); a2[3] = f32_rep2(a.w);
            const ulonglong2* wp = reinterpret_cast<const ulonglong2*>(sW + k * HH + colbase);
            uint64_t w[14];
#pragma unroll
            for (int j = 0; j < 7; j++) { ulonglong2 u = wp[j]; w[2 * j] = u.x; w[2 * j + 1] = u.y; }
#pragma unroll
            for (int i = 0; i < 4; i++)
#pragma unroll
                for (int j = 0; j < 14; j++)
                    acc[i * 14 + j] = f32x2_fma(a2[i], w[j], acc[i * 14 + j]);
        }
    }
    uint64_t sum[14], sq[14];
#pragma unroll
    for (int j = 0; j < 14; j++) { sum[j] = 0ull; sq[j] = 0ull; }
#pragma unroll
    for (int i = 0; i < 4; i++) {
        int row = row0 + rg * 4 + i;
        if (row < M) {
            uint64_t* out = reinterpret_cast<uint64_t*>(C + (long)row * HH + colbase);
#pragma unroll
            for (int j = 0; j < 14; j++) {
                uint64_t v = acc[i * 14 + j];
                out[j] = v;
                sum[j] = f32x2_add(sum[j], v);
                sq[j] = f32x2_fma(v, v, sq[j]);
            }
        }
    }
#pragma unroll
    for (int j = 0; j < 14; j++) {
        float lo, hi;
        f32x2_unpack(sum[j], lo, hi);
        atomicAdd(&sStat[colbase + 2 * j], lo);
        atomicAdd(&sStat[colbase + 2 * j + 1], hi);
        f32x2_unpack(sq[j], lo, hi);
        atomicAdd(&sStat[HH + colbase + 2 * j], lo);
        atomicAdd(&sStat[HH + colbase + 2 * j + 1], hi);
    }
    __syncthreads();
    for (int i = tid; i < 2 * HH; i += 320) atomicAdd(&g_stats[i], sStat[i]);
}

// ---------------- finalize BN stats -> scale/shift; self-zero ----------------
__global__ void finalize_stats(const float* __restrict__ g, const float* __restrict__ be,
                               float invM) {
    int c = threadIdx.x;
    if (c >= HH) return;
    float s = g_stats[c];
    float s2 = g_stats[HH + c];
    g_stats[c] = 0.f;
    g_stats[HH + c] = 0.f;
    float mean = s * invM;
    float var = s2 * invM - mean * mean;
    float rstd = rsqrtf(var + 1e-5f);
    float sc = g[c] * rstd;
    g_scale[c] = sc;
    g_shift[c] = fmaf(-mean, sc, be[c]);
}

// ---------------- scatter: agg[dst[e]] += relu(bn(Y[e])) ----------------
__global__ void scatter_bn_relu(const float* __restrict__ Y, const int* __restrict__ dst,
                                float* __restrict__ agg) {
    long i = (long)blockIdx.x * 256 + threadIdx.x;
    if (i >= (long)EE * (HH / 4)) return;
    int e = (int)(i / (HH / 4));
    int c = (int)(i - (long)e * (HH / 4)) * 4;
    float4 y = *reinterpret_cast<const float4*>(Y + (long)e * HH + c);
    float* p = agg + (long)dst[e] * HH + c;
    float v0 = fmaf(y.x, g_scale[c + 0], g_shift[c + 0]);
    float v1 = fmaf(y.y, g_scale[c + 1], g_shift[c + 1]);
    float v2 = fmaf(y.z, g_scale[c + 2], g_shift[c + 2]);
    float v3 = fmaf(y.w, g_scale[c + 3], g_shift[c + 3]);
    if (v0 > 0.f) atomicAdd(p + 0, v0);
    if (v1 > 0.f) atomicAdd(p + 1, v1);
    if (v2 > 0.f) atomicAdd(p + 2, v2);
    if (v3 > 0.f) atomicAdd(p + 3, v3);
}

// ---------------- residual: h += relu(bn(U)) ----------------
__global__ void residual_bn_relu(const float* __restrict__ U, float* __restrict__ h) {
    int i = blockIdx.x * 256 + threadIdx.x;
    if (i >= NN * HH / 4) return;
    int c = (i % (HH / 4)) * 4;
    float4 u = *reinterpret_cast<const float4*>(U + (long)i * 4);
    float4 hv = *reinterpret_cast<float4*>(h + (long)i * 4);
    hv.x += fmaxf(fmaf(u.x, g_scale[c + 0], g_shift[c + 0]), 0.f);
    hv.y += fmaxf(fmaf(u.y, g_scale[c + 1], g_shift[c + 1]), 0.f);
    hv.z += fmaxf(fmaf(u.z, g_scale[c + 2], g_shift[c + 2]), 0.f);
    hv.w += fmaxf(fmaf(u.w, g_scale[c + 3], g_shift[c + 3]), 0.f);
    *reinterpret_cast<float4*>(h + (long)i * 4) = hv;
}

// ---------------- pooling + head ----------------
__global__ void pool_accum(const float* __restrict__ h, const int* __restrict__ batch,
                           float* __restrict__ pool) {
    int i = blockIdx.x * 256 + threadIdx.x;
    if (i >= NN * HH / 4) return;
    int n = i / (HH / 4);
    int c = (i - n * (HH / 4)) * 4;
    float4 v = *reinterpret_cast<const float4*>(h + (long)i * 4);
    float* p = pool + (long)batch[n] * HH + c;
    atomicAdd(p + 0, v.x);
    atomicAdd(p + 1, v.y);
    atomicAdd(p + 2, v.z);
    atomicAdd(p + 3, v.w);
}

__global__ void pool_count(const int* __restrict__ batch, float* __restrict__ cnt) {
    int n = blockIdx.x * 256 + threadIdx.x;
    if (n < NN) atomicAdd(&cnt[batch[n]], 1.0f);
}

__global__ void head_kernel(const float* __restrict__ pool, const float* __restrict__ cnt,
                            const float* __restrict__ Wmu, const float* __restrict__ bmu,
                            float* __restrict__ out) {
    int gph = blockIdx.x;
    int z = threadIdx.x;
    float inv = 1.0f / fmaxf(cnt[gph], 1.0f);
    float s = bmu[z];
    for (int k = 0; k < HH; k++) s = fmaf(pool[gph * HH + k] * inv, Wmu[k * ZZ + z], s);
    out[gph * ZZ + z] = s;
}

// ---------------- host orchestration ----------------
extern "C" void kernel_launch(void* const* d_in, const int* in_sizes, int n_in,
                              void* d_out, int out_size) {
    const float *x, *edge_attr, *Wi, *bi, *Wm1, *bm1, *g1, *be1, *Wm2, *bm2, *g2, *be2;
    const float *Wu1, *bu1, *g3, *be3, *Wu2, *bu2, *g4, *be4, *Wmu, *bmu;
    const int *edge_index, *batch;

    if (in_sizes[2] == 2 * EE) {
        x = (const float*)d_in[0];   edge_attr = (const float*)d_in[1];
        edge_index = (const int*)d_in[2]; batch = (const int*)d_in[3];
        Wi = (const float*)d_in[4];  bi = (const float*)d_in[5];
        Wm1 = (const float*)d_in[6]; bm1 = (const float*)d_in[7];
        g1 = (const float*)d_in[8];  be1 = (const float*)d_in[9];
        Wm2 = (const float*)d_in[10]; bm2 = (const float*)d_in[11];
        g2 = (const float*)d_in[12]; be2 = (const float*)d_in[13];
        Wu1 = (const float*)d_in[14]; bu1 = (const float*)d_in[15];
        g3 = (const float*)d_in[16]; be3 = (const float*)d_in[17];
        Wu2 = (const float*)d_in[18]; bu2 = (const float*)d_in[19];
        g4 = (const float*)d_in[20]; be4 = (const float*)d_in[21];
        Wmu = (const float*)d_in[22]; bmu = (const float*)d_in[23];
    } else {
        x = (const float*)d_in[0];   edge_attr = (const float*)d_in[1];
        Wi = (const float*)d_in[2];  bi = (const float*)d_in[3];
        Wm1 = (const float*)d_in[4]; bm1 = (const float*)d_in[5];
        g1 = (const float*)d_in[6];  be1 = (const float*)d_in[7];
        Wm2 = (const float*)d_in[8]; bm2 = (const float*)d_in[9];
        g2 = (const float*)d_in[10]; be2 = (const float*)d_in[11];
        Wu1 = (const float*)d_in[12]; bu1 = (const float*)d_in[13];
        g3 = (const float*)d_in[14]; be3 = (const float*)d_in[15];
        Wu2 = (const float*)d_in[16]; bu2 = (const float*)d_in[17];
        g4 = (const float*)d_in[18]; be4 = (const float*)d_in[19];
        Wmu = (const float*)d_in[20]; bmu = (const float*)d_in[21];
        edge_index = (const int*)d_in[22]; batch = (const int*)d_in[23];
    }
    const int* src = edge_index;
    const int* dst = edge_index + EE;

    float *hbuf, *Ybuf, *aggbuf, *Ubuf, *poolbuf, *cntbuf, *statsbuf;
    uint32_t *wb;
    cudaGetSymbolAddress((void**)&hbuf, g_h);
    cudaGetSymbolAddress((void**)&Ybuf, g_Y);
    cudaGetSymbolAddress((void**)&aggbuf, g_agg);
    cudaGetSymbolAddress((void**)&Ubuf, g_U);
    cudaGetSymbolAddress((void**)&poolbuf, g_pool);
    cudaGetSymbolAddress((void**)&cntbuf, g_cnt);
    cudaGetSymbolAddress((void**)&statsbuf, g_stats);
    cudaGetSymbolAddress((void**)&wb, g_wb);

    cudaFuncSetAttribute(gemm1_mma, cudaFuncAttributeMaxDynamicSharedMemorySize, SM_TOT);
    cudaFuncSetAttribute(gemm2_mma, cudaFuncAttributeMaxDynamicSharedMemorySize, SM_TOT);

    const int NH_BLKS = (NN * HH + 255) / 256;
    const int NH4_BLKS = (NN * HH / 4 + 255) / 256;
    const int MSG_BLKS = EE / 128;                    // 2500
    const int UPD_BLKS = (NN + 127) / 128;            // 157
    const long EH4 = (long)EE * (HH / 4);
    const int SC_BLKS = (int)((EH4 + 255) / 256);

    zero4_kernel<<<1, 256>>>((float4*)statsbuf, 2 * HH / 4);
    input_layer<<<NH_BLKS, 256>>>(x, Wi, bi, hbuf);

    for (int l = 0; l < LL; l++) {
        const float* wm1 = Wm1 + (long)l * K_MSG * HH;
        const float* wm2 = Wm2 + (long)l * HH * HH;
        const float* wu1 = Wu1 + (long)l * K_UPD * HH;
        const float* wu2 = Wu2 + (long)l * HH * HH;

        // ---- message MLP on edges (HMMA fp16 tensor cores) ----
        conv_w<<<(9 * 9216) / 256, 256>>>(wm1, K_MSG, 9, wb);
        gemm1_mma<<<MSG_BLKS, 256, SM_TOT>>>(hbuf, dst, src, edge_attr,
                                             wb, bm1 + l * HH, Ybuf);
        finalize_stats<<<1, 288>>>(g1 + l * HH, be1 + l * HH, 1.0f / EE);
        conv_w<<<(5 * 9216) / 256, 256>>>(wm2, HH, 5, wb);
        gemm2_mma<<<MSG_BLKS, 256, SM_TOT>>>(Ybuf, wb, bm2 + l * HH);
        finalize_stats<<<1, 288>>>(g2 + l * HH, be2 + l * HH, 1.0f / EE);

        // ---- aggregate ----
        zero4_kernel<<<NH4_BLKS, 256>>>((float4*)aggbuf, NN * HH / 4);
        scatter_bn_relu<<<SC_BLKS, 256>>>(Ybuf, dst, aggbuf);

        // ---- update MLP on nodes (f32x2 path) ----
        gemm_cat<<<UPD_BLKS, 320>>>(hbuf, aggbuf, wu1, bu1 + l * HH, Ubuf, NN, K_UPD);
        finalize_stats<<<1, 288>>>(g3 + l * HH, be3 + l * HH, 1.0f / NN);
        gemm_inplace<<<UPD_BLKS, 320>>>(Ubuf, wu2, bu2 + l * HH, NN);
        finalize_stats<<<1, 288>>>(g4 + l * HH, be4 + l * HH, 1.0f / NN);
        residual_bn_relu<<<NH4_BLKS, 256>>>(Ubuf, hbuf);
    }

    zero4_kernel<<<(GG * HH / 4 + 255) / 256, 256>>>((float4*)poolbuf, GG * HH / 4);
    zero4_kernel<<<1, 256>>>((float4*)cntbuf, GG / 4);
    pool_accum<<<NH4_BLKS, 256>>>(hbuf, batch, poolbuf);
    pool_count<<<(NN + 255) / 256, 256>>>(batch, cntbuf);
    head_kernel<<<GG, ZZ>>>(poolbuf, cntbuf, Wmu, bmu, (float*)d_out);
}

// round 11
// speedup vs baseline: 1.2818x; 1.0881x over previous
#include <cuda_runtime.h>
#include <cuda_fp16.h>
#include <cstdint>

#define NN 20000
#define EE 320000
#define HH 280
#define GG 64
#define NFF 5
#define EFF 4
#define LL 3
#define ZZ 64
#define K_MSG 564   // 2H + EF
#define K_UPD 560   // 2H

// ---------------- scratch (static device globals; no runtime alloc) ----------------
__device__ float g_h[NN * HH];
__device__ float g_Y[EE * HH];
__device__ float g_agg[NN * HH];
__device__ float g_U[NN * HH];
__device__ float g_stats[2 * HH];
__device__ float g_scale[HH];
__device__ float g_shift[HH];
__device__ float g_pool[GG * HH];
__device__ float g_cnt[GG];
// pre-converted W image: per 64-k chunk, [288 n][64 k] fp16, 128B rows, SW128-swizzled
__device__ uint32_t g_wb[9 * 9216];

// ================= helpers =================
__device__ __forceinline__ uint32_t smem_u32(const void* p) {
    uint32_t a;
    asm("{ .reg .u64 t; cvta.to.shared.u64 t, %1; cvt.u32.u64 %0, t; }" : "=r"(a) : "l"(p));
    return a;
}
#define SWZ(o) ((o) ^ (((o) >> 3) & 0x70))

__device__ __forceinline__ void ldsm_x4(uint32_t* r, uint32_t addr) {
    asm volatile("ldmatrix.sync.aligned.m8n8.x4.shared.b16 {%0,%1,%2,%3}, [%4];"
                 : "=r"(r[0]), "=r"(r[1]), "=r"(r[2]), "=r"(r[3]) : "r"(addr));
}
__device__ __forceinline__ void mma_f16(float* d, const uint32_t* a, uint32_t b0, uint32_t b1) {
    asm volatile("mma.sync.aligned.m16n8k16.row.col.f32.f16.f16.f32 "
                 "{%0,%1,%2,%3}, {%4,%5,%6,%7}, {%8,%9}, {%0,%1,%2,%3};"
                 : "+f"(d[0]), "+f"(d[1]), "+f"(d[2]), "+f"(d[3])
                 : "r"(a[0]), "r"(a[1]), "r"(a[2]), "r"(a[3]), "r"(b0), "r"(b1));
}

// smem layout (bytes)
#define SM_STAT  0         // 560 floats
#define SM_I0    2304      // 128 ints
#define SM_I1    2816
#define SM_SC    3328      // 280 floats (inplace)
#define SM_SH    4480
#define SM_AH    8192      // 128x64 fp16 swizzled (16KB)
#define SM_AL    24576     // 16KB
#define SM_BH    40960     // 288x64 fp16 swizzled (36KB)
#define SM_TOT   78848

// ---------------- misc kernels ----------------
__global__ void zero4_kernel(float4* __restrict__ p, int n4) {
    int i = blockIdx.x * 256 + threadIdx.x;
    if (i < n4) p[i] = make_float4(0.f, 0.f, 0.f, 0.f);
}

__global__ void input_layer(const float* __restrict__ x, const float* __restrict__ Wi,
                            const float* __restrict__ bi, float* __restrict__ h) {
    int idx = blockIdx.x * 256 + threadIdx.x;
    if (idx >= NN * HH) return;
    int n = idx / HH;
    int c = idx - n * HH;
    float s = bi[c];
#pragma unroll
    for (int f = 0; f < NFF; f++) s = fmaf(x[n * NFF + f], Wi[f * HH + c], s);
    h[idx] = s;
}

// ---------------- W pre-conversion: fp32 [K,280] -> swizzled fp16 chunk image ----
__global__ void conv_w(const float* __restrict__ W, int K, int nCh,
                       uint32_t* __restrict__ ob) {
    int i = blockIdx.x * 256 + threadIdx.x;
    if (i >= nCh * 9216) return;
    int ch = i / 9216;
    int rem = i - ch * 9216;
    int kp = rem / 288;          // 0..31 (pair of k)
    int n = rem - kp * 288;      // 0..287
    int k0 = ch * 64 + 2 * kp;
    float v0 = (k0 < K && n < HH) ? W[(long)k0 * HH + n] : 0.f;
    float v1 = (k0 + 1 < K && n < HH) ? W[(long)(k0 + 1) * HH + n] : 0.f;
    __half2 hv = __floats2half2_rn(v0, v1);
    uint32_t off = SWZ((uint32_t)(n * 128 + kp * 4));
    ob[ch * 9216 + (off >> 2)] = *reinterpret_cast<uint32_t*>(&hv);
}

// ============================================================================
// HMMA compute core: one 64-k chunk, warp tile 16 rows x 144 cols, fp16
// 2-product split (A_hi*B + A_lo*B). 16 warps: wm 0..7 (rows), wn 0..1 (cols).
// ============================================================================
__device__ __forceinline__ void hmma_chunk(uint32_t sb, int wm, int wn,
                                           int lane, float acc[18][4]) {
    const uint32_t abase = sb + SM_AH;
    const uint32_t bbase = sb + SM_BH;
#pragma unroll
    for (int ks = 0; ks < 4; ks++) {
        uint32_t ah[4], al[4];
        {
            int row = wm * 16 + (lane & 15);
            int koff = ks * 32 + ((lane >> 4) << 4);
            uint32_t o = SWZ((uint32_t)(row * 128 + koff));
            ldsm_x4(ah, abase + o);
            ldsm_x4(al, abase + 16384 + o);
        }
        int bkoff = ks * 32 + ((lane >> 3) & 1) * 16;
        int bn0 = wn * 144 + ((lane >> 4) << 3) + (lane & 7);
#pragma unroll
        for (int g = 0; g < 5; g++) {
            const int nta = 2 * g, ntb = 2 * g + 1;
            uint32_t ba[4], bb[4];
            ldsm_x4(ba, bbase + SWZ((uint32_t)((bn0 + nta * 16) * 128 + bkoff)));
            if (g < 4) ldsm_x4(bb, bbase + SWZ((uint32_t)((bn0 + ntb * 16) * 128 + bkoff)));
#pragma unroll
            for (int p = 0; p < 2; p++)
                mma_f16(acc[nta * 2 + p], ah, ba[2 * p], ba[2 * p + 1]);
            if (g < 4) {
#pragma unroll
                for (int p = 0; p < 2; p++)
                    mma_f16(acc[ntb * 2 + p], ah, bb[2 * p], bb[2 * p + 1]);
            }
#pragma unroll
            for (int p = 0; p < 2; p++)
                mma_f16(acc[nta * 2 + p], al, ba[2 * p], ba[2 * p + 1]);
            if (g < 4) {
#pragma unroll
                for (int p = 0; p < 2; p++)
                    mma_f16(acc[ntb * 2 + p], al, bb[2 * p], bb[2 * p + 1]);
            }
        }
    }
}

// Epilogue: bias + guarded store + fused BN stats.
__device__ __forceinline__ void hmma_epilogue(float acc[18][4], long row0, int wm, int wn,
                                              int lane, const float* __restrict__ bias,
                                              float* __restrict__ Cout, float* sStat, int M) {
    int rbase = wm * 16 + (lane >> 2);
    int cbase = wn * 144 + (lane & 3) * 2;
    long r1 = row0 + rbase;
    long r2 = r1 + 8;
    bool ok1 = r1 < M, ok2 = r2 < M;
#pragma unroll
    for (int nt = 0; nt < 18; nt++) {
        int c = cbase + nt * 8;
        if (c < HH) {
            float b0 = bias[c], b1 = bias[c + 1];
            float v0 = acc[nt][0] + b0;
            float v1 = acc[nt][1] + b1;
            float v2 = acc[nt][2] + b0;
            float v3 = acc[nt][3] + b1;
            float s0 = 0.f, s1 = 0.f, q0 = 0.f, q1 = 0.f;
            if (ok1) {
                *reinterpret_cast<float2*>(Cout + r1 * HH + c) = make_float2(v0, v1);
                s0 += v0; s1 += v1; q0 += v0 * v0; q1 += v1 * v1;
            }
            if (ok2) {
                *reinterpret_cast<float2*>(Cout + r2 * HH + c) = make_float2(v2, v3);
                s0 += v2; s1 += v3; q0 += v2 * v2; q1 += v3 * v3;
            }
            if (ok1 || ok2) {
                atomicAdd(&sStat[c], s0);
                atomicAdd(&sStat[c + 1], s1);
                atomicAdd(&sStat[HH + c], q0);
                atomicAdd(&sStat[HH + c + 1], q1);
            }
        }
    }
}

// ============================================================================
// Unified GEMM1: C[M,280] = cat(A0[idx0], A1[idx1], ea?) @ W[K,280] + b
// Edges: (h, dst, h, src, ea, K=564). Nodes: (h, null, agg, null, null, K=560).
// ============================================================================
__global__ void __launch_bounds__(512)
gemm_cat_mma(const float* __restrict__ A0, const int* __restrict__ idx0,
             const float* __restrict__ A1, const int* __restrict__ idx1,
             const float* __restrict__ ea,
             const uint32_t* __restrict__ wb,
             const float* __restrict__ bias, float* __restrict__ Cout,
             int M, int K, int nCh) {
    extern __shared__ char sm[];
    uint32_t sb = smem_u32(sm);
    const int tid = threadIdx.x, wid = tid >> 5, lane = tid & 31;
    const int wm = wid >> 1, wn = wid & 1;
    const long row0 = (long)blockIdx.x * 128;
    int* sI0 = (int*)(sm + SM_I0);
    int* sI1 = (int*)(sm + SM_I1);
    float* sStat = (float*)(sm + SM_STAT);

    for (int i = tid; i < 2 * HH; i += 512) sStat[i] = 0.f;
    if (tid < 128) {
        int e = (int)min(row0 + tid, (long)M - 1);
        sI0[tid] = idx0 ? idx0[e] : e;
        sI1[tid] = idx1 ? idx1[e] : e;
    }
    float acc[18][4];
#pragma unroll
    for (int nt = 0; nt < 18; nt++)
#pragma unroll
        for (int j = 0; j < 4; j++) acc[nt][j] = 0.f;
    __syncthreads();

    for (int ch = 0; ch < nCh; ++ch) {
        if (ch) __syncthreads();
        const int kbase = ch * 64;
        // ---- stage A (gathered, fp32 -> hi/lo fp16, swizzled) ----
        for (int i = tid; i < 4096; i += 512) {
            int r = i >> 5, kp = i & 31;
            int c = kbase + 2 * kp;
            float2 v = make_float2(0.f, 0.f);
            if (c < HH)            v = *(const float2*)(A0 + (long)sI0[r] * HH + c);
            else if (c < 2 * HH)   v = *(const float2*)(A1 + (long)sI1[r] * HH + (c - HH));
            else if (c < K)        v = *(const float2*)(ea + (row0 + r) * EFF + (c - 2 * HH));
            __half2 hv = __floats2half2_rn(v.x, v.y);
            float2 hf = __half22float2(hv);
            __half2 lv = __floats2half2_rn(v.x - hf.x, v.y - hf.y);
            uint32_t off = SWZ((uint32_t)(r * 128 + kp * 4));
            *(uint32_t*)(sm + SM_AH + off) = *reinterpret_cast<uint32_t*>(&hv);
            *(uint32_t*)(sm + SM_AL + off) = *reinterpret_cast<uint32_t*>(&lv);
        }
        // ---- stage B (float4 copy of pre-swizzled fp16 image) ----
        {
            const float4* s1 = (const float4*)(wb + ch * 9216);
            float4* d1 = (float4*)(sm + SM_BH);
            for (int i = tid; i < 2304; i += 512) d1[i] = s1[i];
        }
        __syncthreads();
        hmma_chunk(sb, wm, wn, lane, acc);
    }

    hmma_epilogue(acc, row0, wm, wn, lane, bias, Cout, sStat, M);
    __syncthreads();
    for (int i = tid; i < 2 * HH; i += 512) atomicAdd(&g_stats[i], sStat[i]);
}

// ============================================================================
// Unified GEMM2 (in place): C[M,280] = relu(bn(C)) @ W[280,280] + b
// ============================================================================
__global__ void __launch_bounds__(512)
gemm_inplace_mma(float* __restrict__ C, const uint32_t* __restrict__ wb,
                 const float* __restrict__ bias, int M) {
    extern __shared__ char sm[];
    uint32_t sb = smem_u32(sm);
    const int tid = threadIdx.x, wid = tid >> 5, lane = tid & 31;
    const int wm = wid >> 1, wn = wid & 1;
    const long row0 = (long)blockIdx.x * 128;
    float* sStat = (float*)(sm + SM_STAT);
    float* sSc = (float*)(sm + SM_SC);
    float* sSh = (float*)(sm + SM_SH);

    for (int i = tid; i < 2 * HH; i += 512) sStat[i] = 0.f;
    for (int i = tid; i < HH; i += 512) { sSc[i] = g_scale[i]; sSh[i] = g_shift[i]; }
    float acc[18][4];
#pragma unroll
    for (int nt = 0; nt < 18; nt++)
#pragma unroll
        for (int j = 0; j < 4; j++) acc[nt][j] = 0.f;
    __syncthreads();

    for (int ch = 0; ch < 5; ++ch) {
        if (ch) __syncthreads();
        const int kbase = ch * 64;
        for (int i = tid; i < 4096; i += 512) {
            int r = i >> 5, kp = i & 31;
            int c = kbase + 2 * kp;
            float2 v = make_float2(0.f, 0.f);
            if (c < HH) {
                long row = min(row0 + r, (long)M - 1);
                float2 y = *(const float2*)(C + row * HH + c);
                v.x = fmaxf(fmaf(y.x, sSc[c], sSh[c]), 0.f);
                v.y = fmaxf(fmaf(y.y, sSc[c + 1], sSh[c + 1]), 0.f);
            }
            __half2 hv = __floats2half2_rn(v.x, v.y);
            float2 hf = __half22float2(hv);
            __half2 lv = __floats2half2_rn(v.x - hf.x, v.y - hf.y);
            uint32_t off = SWZ((uint32_t)(r * 128 + kp * 4));
            *(uint32_t*)(sm + SM_AH + off) = *reinterpret_cast<uint32_t*>(&hv);
            *(uint32_t*)(sm + SM_AL + off) = *reinterpret_cast<uint32_t*>(&lv);
        }
        {
            const float4* s1 = (const float4*)(wb + ch * 9216);
            float4* d1 = (float4*)(sm + SM_BH);
            for (int i = tid; i < 2304; i += 512) d1[i] = s1[i];
        }
        __syncthreads();
        hmma_chunk(sb, wm, wn, lane, acc);
    }

    hmma_epilogue(acc, row0, wm, wn, lane, bias, C, sStat, M);
    __syncthreads();
    for (int i = tid; i < 2 * HH; i += 512) atomicAdd(&g_stats[i], sStat[i]);
}

// ---------------- finalize BN stats -> scale/shift; self-zero ----------------
__global__ void finalize_stats(const float* __restrict__ g, const float* __restrict__ be,
                               float invM) {
    int c = threadIdx.x;
    if (c >= HH) return;
    float s = g_stats[c];
    float s2 = g_stats[HH + c];
    g_stats[c] = 0.f;
    g_stats[HH + c] = 0.f;
    float mean = s * invM;
    float var = s2 * invM - mean * mean;
    float rstd = rsqrtf(var + 1e-5f);
    float sc = g[c] * rstd;
    g_scale[c] = sc;
    g_shift[c] = fmaf(-mean, sc, be[c]);
}

// ---------------- scatter: agg[dst[e]] += relu(bn(Y[e])) ----------------
__global__ void scatter_bn_relu(const float* __restrict__ Y, const int* __restrict__ dst,
                                float* __restrict__ agg) {
    long i = (long)blockIdx.x * 256 + threadIdx.x;
    if (i >= (long)EE * (HH / 4)) return;
    int e = (int)(i / (HH / 4));
    int c = (int)(i - (long)e * (HH / 4)) * 4;
    float4 y = *reinterpret_cast<const float4*>(Y + (long)e * HH + c);
    float* p = agg + (long)dst[e] * HH + c;
    float v0 = fmaf(y.x, g_scale[c + 0], g_shift[c + 0]);
    float v1 = fmaf(y.y, g_scale[c + 1], g_shift[c + 1]);
    float v2 = fmaf(y.z, g_scale[c + 2], g_shift[c + 2]);
    float v3 = fmaf(y.w, g_scale[c + 3], g_shift[c + 3]);
    if (v0 > 0.f) atomicAdd(p + 0, v0);
    if (v1 > 0.f) atomicAdd(p + 1, v1);
    if (v2 > 0.f) atomicAdd(p + 2, v2);
    if (v3 > 0.f) atomicAdd(p + 3, v3);
}

// ---------------- residual: h += relu(bn(U)) ----------------
__global__ void residual_bn_relu(const float* __restrict__ U, float* __restrict__ h) {
    int i = blockIdx.x * 256 + threadIdx.x;
    if (i >= NN * HH / 4) return;
    int c = (i % (HH / 4)) * 4;
    float4 u = *reinterpret_cast<const float4*>(U + (long)i * 4);
    float4 hv = *reinterpret_cast<float4*>(h + (long)i * 4);
    hv.x += fmaxf(fmaf(u.x, g_scale[c + 0], g_shift[c + 0]), 0.f);
    hv.y += fmaxf(fmaf(u.y, g_scale[c + 1], g_shift[c + 1]), 0.f);
    hv.z += fmaxf(fmaf(u.z, g_scale[c + 2], g_shift[c + 2]), 0.f);
    hv.w += fmaxf(fmaf(u.w, g_scale[c + 3], g_shift[c + 3]), 0.f);
    *reinterpret_cast<float4*>(h + (long)i * 4) = hv;
}

// ---------------- pooling + head ----------------
__global__ void pool_accum(const float* __restrict__ h, const int* __restrict__ batch,
                           float* __restrict__ pool) {
    int i = blockIdx.x * 256 + threadIdx.x;
    if (i >= NN * HH / 4) return;
    int n = i / (HH / 4);
    int c = (i - n * (HH / 4)) * 4;
    float4 v = *reinterpret_cast<const float4*>(h + (long)i * 4);
    float* p = pool + (long)batch[n] * HH + c;
    atomicAdd(p + 0, v.x);
    atomicAdd(p + 1, v.y);
    atomicAdd(p + 2, v.z);
    atomicAdd(p + 3, v.w);
}

__global__ void pool_count(const int* __restrict__ batch, float* __restrict__ cnt) {
    int n = blockIdx.x * 256 + threadIdx.x;
    if (n < NN) atomicAdd(&cnt[batch[n]], 1.0f);
}

__global__ void head_kernel(const float* __restrict__ pool, const float* __restrict__ cnt,
                            const float* __restrict__ Wmu, const float* __restrict__ bmu,
                            float* __restrict__ out) {
    int gph = blockIdx.x;
    int z = threadIdx.x;
    float inv = 1.0f / fmaxf(cnt[gph], 1.0f);
    float s = bmu[z];
    for (int k = 0; k < HH; k++) s = fmaf(pool[gph * HH + k] * inv, Wmu[k * ZZ + z], s);
    out[gph * ZZ + z] = s;
}

// ---------------- host orchestration ----------------
extern "C" void kernel_launch(void* const* d_in, const int* in_sizes, int n_in,
                              void* d_out, int out_size) {
    const float *x, *edge_attr, *Wi, *bi, *Wm1, *bm1, *g1, *be1, *Wm2, *bm2, *g2, *be2;
    const float *Wu1, *bu1, *g3, *be3, *Wu2, *bu2, *g4, *be4, *Wmu, *bmu;
    const int *edge_index, *batch;

    if (in_sizes[2] == 2 * EE) {
        x = (const float*)d_in[0];   edge_attr = (const float*)d_in[1];
        edge_index = (const int*)d_in[2]; batch = (const int*)d_in[3];
        Wi = (const float*)d_in[4];  bi = (const float*)d_in[5];
        Wm1 = (const float*)d_in[6]; bm1 = (const float*)d_in[7];
        g1 = (const float*)d_in[8];  be1 = (const float*)d_in[9];
        Wm2 = (const float*)d_in[10]; bm2 = (const float*)d_in[11];
        g2 = (const float*)d_in[12]; be2 = (const float*)d_in[13];
        Wu1 = (const float*)d_in[14]; bu1 = (const float*)d_in[15];
        g3 = (const float*)d_in[16]; be3 = (const float*)d_in[17];
        Wu2 = (const float*)d_in[18]; bu2 = (const float*)d_in[19];
        g4 = (const float*)d_in[20]; be4 = (const float*)d_in[21];
        Wmu = (const float*)d_in[22]; bmu = (const float*)d_in[23];
    } else {
        x = (const float*)d_in[0];   edge_attr = (const float*)d_in[1];
        Wi = (const float*)d_in[2];  bi = (const float*)d_in[3];
        Wm1 = (const float*)d_in[4]; bm1 = (const float*)d_in[5];
        g1 = (const float*)d_in[6];  be1 = (const float*)d_in[7];
        Wm2 = (const float*)d_in[8]; bm2 = (const float*)d_in[9];
        g2 = (const float*)d_in[10]; be2 = (const float*)d_in[11];
        Wu1 = (const float*)d_in[12]; bu1 = (const float*)d_in[13];
        g3 = (const float*)d_in[14]; be3 = (const float*)d_in[15];
        Wu2 = (const float*)d_in[16]; bu2 = (const float*)d_in[17];
        g4 = (const float*)d_in[18]; be4 = (const float*)d_in[19];
        Wmu = (const float*)d_in[20]; bmu = (const float*)d_in[21];
        edge_index = (const int*)d_in[22]; batch = (const int*)d_in[23];
    }
    const int* src = edge_index;
    const int* dst = edge_index + EE;

    float *hbuf, *Ybuf, *aggbuf, *Ubuf, *poolbuf, *cntbuf, *statsbuf;
    uint32_t *wb;
    cudaGetSymbolAddress((void**)&hbuf, g_h);
    cudaGetSymbolAddress((void**)&Ybuf, g_Y);
    cudaGetSymbolAddress((void**)&aggbuf, g_agg);
    cudaGetSymbolAddress((void**)&Ubuf, g_U);
    cudaGetSymbolAddress((void**)&poolbuf, g_pool);
    cudaGetSymbolAddress((void**)&cntbuf, g_cnt);
    cudaGetSymbolAddress((void**)&statsbuf, g_stats);
    cudaGetSymbolAddress((void**)&wb, g_wb);

    cudaFuncSetAttribute(gemm_cat_mma, cudaFuncAttributeMaxDynamicSharedMemorySize, SM_TOT);
    cudaFuncSetAttribute(gemm_inplace_mma, cudaFuncAttributeMaxDynamicSharedMemorySize, SM_TOT);

    const int NH_BLKS = (NN * HH + 255) / 256;
    const int NH4_BLKS = (NN * HH / 4 + 255) / 256;
    const int MSG_BLKS = EE / 128;                    // 2500
    const int UPD_BLKS = (NN + 127) / 128;            // 157
    const long EH4 = (long)EE * (HH / 4);
    const int SC_BLKS = (int)((EH4 + 255) / 256);

    zero4_kernel<<<1, 256>>>((float4*)statsbuf, 2 * HH / 4);
    input_layer<<<NH_BLKS, 256>>>(x, Wi, bi, hbuf);

    for (int l = 0; l < LL; l++) {
        const float* wm1 = Wm1 + (long)l * K_MSG * HH;
        const float* wm2 = Wm2 + (long)l * HH * HH;
        const float* wu1 = Wu1 + (long)l * K_UPD * HH;
        const float* wu2 = Wu2 + (long)l * HH * HH;

        // ---- message MLP on edges (HMMA fp16) ----
        conv_w<<<(9 * 9216) / 256, 256>>>(wm1, K_MSG, 9, wb);
        gemm_cat_mma<<<MSG_BLKS, 512, SM_TOT>>>(hbuf, dst, hbuf, src, edge_attr,
                                                wb, bm1 + l * HH, Ybuf, EE, K_MSG, 9);
        finalize_stats<<<1, 288>>>(g1 + l * HH, be1 + l * HH, 1.0f / EE);
        conv_w<<<(5 * 9216) / 256, 256>>>(wm2, HH, 5, wb);
        gemm_inplace_mma<<<MSG_BLKS, 512, SM_TOT>>>(Ybuf, wb, bm2 + l * HH, EE);
        finalize_stats<<<1, 288>>>(g2 + l * HH, be2 + l * HH, 1.0f / EE);

        // ---- aggregate ----
        zero4_kernel<<<NH4_BLKS, 256>>>((float4*)aggbuf, NN * HH / 4);
        scatter_bn_relu<<<SC_BLKS, 256>>>(Ybuf, dst, aggbuf);

        // ---- update MLP on nodes (HMMA fp16, identity gather) ----
        conv_w<<<(9 * 9216) / 256, 256>>>(wu1, K_UPD, 9, wb);
        gemm_cat_mma<<<UPD_BLKS, 512, SM_TOT>>>(hbuf, nullptr, aggbuf, nullptr, nullptr,
                                                wb, bu1 + l * HH, Ubuf, NN, K_UPD, 9);
        finalize_stats<<<1, 288>>>(g3 + l * HH, be3 + l * HH, 1.0f / NN);
        conv_w<<<(5 * 9216) / 256, 256>>>(wu2, HH, 5, wb);
        gemm_inplace_mma<<<UPD_BLKS, 512, SM_TOT>>>(Ubuf, wb, bu2 + l * HH, NN);
        finalize_stats<<<1, 288>>>(g4 + l * HH, be4 + l * HH, 1.0f / NN);
        residual_bn_relu<<<NH4_BLKS, 256>>>(Ubuf, hbuf);
    }

    zero4_kernel<<<(GG * HH / 4 + 255) / 256, 256>>>((float4*)poolbuf, GG * HH / 4);
    zero4_kernel<<<1, 256>>>((float4*)cntbuf, GG / 4);
    pool_accum<<<NH4_BLKS, 256>>>(hbuf, batch, poolbuf);
    pool_count<<<(NN + 255) / 256, 256>>>(batch, cntbuf);
    head_kernel<<<GG, ZZ>>>(poolbuf, cntbuf, Wmu, bmu, (float*)d_out);
}

// round 12
// speedup vs baseline: 1.4709x; 1.1476x over previous
#include <cuda_runtime.h>
#include <cuda_fp16.h>
#include <cstdint>

#define NN 20000
#define EE 320000
#define HH 280
#define GG 64
#define NFF 5
#define EFF 4
#define LL 3
#define ZZ 64
#define K_MSG 564   // 2H + EF
#define K_UPD 560   // 2H

// ---------------- scratch (static device globals; no runtime alloc) ----------------
__device__ float g_h[NN * HH];
__device__ float g_Y[EE * HH];
__device__ float g_agg[NN * HH];
__device__ float g_U[NN * HH];
__device__ float g_stats[2 * HH];
__device__ float g_scale[HH];
__device__ float g_shift[HH];
__device__ float g_pool[GG * HH];
__device__ float g_cnt[GG];
// pre-converted W images for ALL layers/weights: 28 chunks per layer
// layout per layer: wm1[9] wm2[5] wu1[9] wu2[5]; each chunk 9216 uint32
__device__ uint32_t g_wb[LL * 28 * 9216];

// ================= helpers =================
__device__ __forceinline__ uint32_t smem_u32(const void* p) {
    uint32_t a;
    asm("{ .reg .u64 t; cvta.to.shared.u64 t, %1; cvt.u32.u64 %0, t; }" : "=r"(a) : "l"(p));
    return a;
}
#define SWZ(o) ((o) ^ (((o) >> 3) & 0x70))

__device__ __forceinline__ void ldsm_x4(uint32_t* r, uint32_t addr) {
    asm volatile("ldmatrix.sync.aligned.m8n8.x4.shared.b16 {%0,%1,%2,%3}, [%4];"
                 : "=r"(r[0]), "=r"(r[1]), "=r"(r[2]), "=r"(r[3]) : "r"(addr));
}
__device__ __forceinline__ void mma_f16(float* d, const uint32_t* a, uint32_t b0, uint32_t b1) {
    asm volatile("mma.sync.aligned.m16n8k16.row.col.f32.f16.f16.f32 "
                 "{%0,%1,%2,%3}, {%4,%5,%6,%7}, {%8,%9}, {%0,%1,%2,%3};"
                 : "+f"(d[0]), "+f"(d[1]), "+f"(d[2]), "+f"(d[3])
                 : "r"(a[0]), "r"(a[1]), "r"(a[2]), "r"(a[3]), "r"(b0), "r"(b1));
}

// smem layout (bytes) — 64-row A tile, total 60KB -> 2 blocks/SM
#define SM_STAT  0         // 560 floats (2240B)
#define SM_I0    2304      // 64 ints
#define SM_I1    2560
#define SM_SC    2816      // 280 floats
#define SM_SH    3936
#define SM_AH    8192      // 64x64 fp16 swizzled (8KB)
#define SM_AL    16384     // 8KB
#define SM_BH    24576     // 288x64 fp16 swizzled (36KB)
#define SM_TOT   61440

// ---------------- misc kernels ----------------
__global__ void zero4_kernel(float4* __restrict__ p, int n4) {
    int i = blockIdx.x * 256 + threadIdx.x;
    if (i < n4) p[i] = make_float4(0.f, 0.f, 0.f, 0.f);
}

__global__ void input_layer(const float* __restrict__ x, const float* __restrict__ Wi,
                            const float* __restrict__ bi, float* __restrict__ h) {
    int idx = blockIdx.x * 256 + threadIdx.x;
    if (idx >= NN * HH) return;
    int n = idx / HH;
    int c = idx - n * HH;
    float s = bi[c];
#pragma unroll
    for (int f = 0; f < NFF; f++) s = fmaf(x[n * NFF + f], Wi[f * HH + c], s);
    h[idx] = s;
}

// ---------------- W pre-conversion: fp32 [K,280] -> swizzled fp16 chunk image ----
__global__ void conv_w(const float* __restrict__ W, int K, int nCh,
                       uint32_t* __restrict__ ob) {
    int i = blockIdx.x * 256 + threadIdx.x;
    if (i >= nCh * 9216) return;
    int ch = i / 9216;
    int rem = i - ch * 9216;
    int kp = rem / 288;          // 0..31 (pair of k)
    int n = rem - kp * 288;      // 0..287
    int k0 = ch * 64 + 2 * kp;
    float v0 = (k0 < K && n < HH) ? W[(long)k0 * HH + n] : 0.f;
    float v1 = (k0 + 1 < K && n < HH) ? W[(long)(k0 + 1) * HH + n] : 0.f;
    __half2 hv = __floats2half2_rn(v0, v1);
    uint32_t off = SWZ((uint32_t)(n * 128 + kp * 4));
    ob[ch * 9216 + (off >> 2)] = *reinterpret_cast<uint32_t*>(&hv);
}

// ============================================================================
// HMMA compute core: one 64-k chunk, warp tile 16 rows x 144 cols, fp16
// 2-product split (A_hi*B + A_lo*B). 8 warps: wm 0..3 (rows), wn 0..1 (cols).
// ============================================================================
__device__ __forceinline__ void hmma_chunk(uint32_t sb, int wm, int wn,
                                           int lane, float acc[18][4]) {
    const uint32_t abase = sb + SM_AH;
    const uint32_t bbase = sb + SM_BH;
#pragma unroll
    for (int ks = 0; ks < 4; ks++) {
        uint32_t ah[4], al[4];
        {
            int row = wm * 16 + (lane & 15);
            int koff = ks * 32 + ((lane >> 4) << 4);
            uint32_t o = SWZ((uint32_t)(row * 128 + koff));
            ldsm_x4(ah, abase + o);
            ldsm_x4(al, abase + 8192 + o);
        }
        int bkoff = ks * 32 + ((lane >> 3) & 1) * 16;
        int bn0 = wn * 144 + ((lane >> 4) << 3) + (lane & 7);
#pragma unroll
        for (int g = 0; g < 5; g++) {
            const int nta = 2 * g, ntb = 2 * g + 1;
            uint32_t ba[4], bb[4];
            ldsm_x4(ba, bbase + SWZ((uint32_t)((bn0 + nta * 16) * 128 + bkoff)));
            if (g < 4) ldsm_x4(bb, bbase + SWZ((uint32_t)((bn0 + ntb * 16) * 128 + bkoff)));
#pragma unroll
            for (int p = 0; p < 2; p++)
                mma_f16(acc[nta * 2 + p], ah, ba[2 * p], ba[2 * p + 1]);
            if (g < 4) {
#pragma unroll
                for (int p = 0; p < 2; p++)
                    mma_f16(acc[ntb * 2 + p], ah, bb[2 * p], bb[2 * p + 1]);
            }
#pragma unroll
            for (int p = 0; p < 2; p++)
                mma_f16(acc[nta * 2 + p], al, ba[2 * p], ba[2 * p + 1]);
            if (g < 4) {
#pragma unroll
                for (int p = 0; p < 2; p++)
                    mma_f16(acc[ntb * 2 + p], al, bb[2 * p], bb[2 * p + 1]);
            }
        }
    }
}

// Epilogue: bias + guarded store + fused BN stats.
__device__ __forceinline__ void hmma_epilogue(float acc[18][4], long row0, int wm, int wn,
                                              int lane, const float* __restrict__ bias,
                                              float* __restrict__ Cout, float* sStat, int M) {
    int rbase = wm * 16 + (lane >> 2);
    int cbase = wn * 144 + (lane & 3) * 2;
    long r1 = row0 + rbase;
    long r2 = r1 + 8;
    bool ok1 = r1 < M, ok2 = r2 < M;
#pragma unroll
    for (int nt = 0; nt < 18; nt++) {
        int c = cbase + nt * 8;
        if (c < HH) {
            float b0 = bias[c], b1 = bias[c + 1];
            float v0 = acc[nt][0] + b0;
            float v1 = acc[nt][1] + b1;
            float v2 = acc[nt][2] + b0;
            float v3 = acc[nt][3] + b1;
            float s0 = 0.f, s1 = 0.f, q0 = 0.f, q1 = 0.f;
            if (ok1) {
                *reinterpret_cast<float2*>(Cout + r1 * HH + c) = make_float2(v0, v1);
                s0 += v0; s1 += v1; q0 += v0 * v0; q1 += v1 * v1;
            }
            if (ok2) {
                *reinterpret_cast<float2*>(Cout + r2 * HH + c) = make_float2(v2, v3);
                s0 += v2; s1 += v3; q0 += v2 * v2; q1 += v3 * v3;
            }
            if (ok1 || ok2) {
                atomicAdd(&sStat[c], s0);
                atomicAdd(&sStat[c + 1], s1);
                atomicAdd(&sStat[HH + c], q0);
                atomicAdd(&sStat[HH + c + 1], q1);
            }
        }
    }
}

// ============================================================================
// Unified GEMM1: C[M,280] = cat(A0[idx0], A1[idx1], ea?) @ W[K,280] + b
// 64 rows per block, 256 threads, 2 blocks/SM.
// ============================================================================
__global__ void __launch_bounds__(256, 2)
gemm_cat_mma(const float* __restrict__ A0, const int* __restrict__ idx0,
             const float* __restrict__ A1, const int* __restrict__ idx1,
             const float* __restrict__ ea,
             const uint32_t* __restrict__ wb,
             const float* __restrict__ bias, float* __restrict__ Cout,
             int M, int K, int nCh) {
    extern __shared__ char sm[];
    uint32_t sb = smem_u32(sm);
    const int tid = threadIdx.x, wid = tid >> 5, lane = tid & 31;
    const int wm = wid >> 1, wn = wid & 1;
    const long row0 = (long)blockIdx.x * 64;
    int* sI0 = (int*)(sm + SM_I0);
    int* sI1 = (int*)(sm + SM_I1);
    float* sStat = (float*)(sm + SM_STAT);

    for (int i = tid; i < 2 * HH; i += 256) sStat[i] = 0.f;
    if (tid < 64) {
        int e = (int)min(row0 + tid, (long)M - 1);
        sI0[tid] = idx0 ? idx0[e] : e;
        sI1[tid] = idx1 ? idx1[e] : e;
    }
    float acc[18][4];
#pragma unroll
    for (int nt = 0; nt < 18; nt++)
#pragma unroll
        for (int j = 0; j < 4; j++) acc[nt][j] = 0.f;
    __syncthreads();

    for (int ch = 0; ch < nCh; ++ch) {
        if (ch) __syncthreads();
        const int kbase = ch * 64;
        // ---- stage A (gathered, fp32 -> hi/lo fp16, swizzled): 64x32 float2 ----
        for (int i = tid; i < 2048; i += 256) {
            int r = i >> 5, kp = i & 31;
            int c = kbase + 2 * kp;
            float2 v = make_float2(0.f, 0.f);
            if (c < HH)            v = *(const float2*)(A0 + (long)sI0[r] * HH + c);
            else if (c < 2 * HH)   v = *(const float2*)(A1 + (long)sI1[r] * HH + (c - HH));
            else if (c < K)        v = *(const float2*)(ea + (row0 + r) * EFF + (c - 2 * HH));
            __half2 hv = __floats2half2_rn(v.x, v.y);
            float2 hf = __half22float2(hv);
            __half2 lv = __floats2half2_rn(v.x - hf.x, v.y - hf.y);
            uint32_t off = SWZ((uint32_t)(r * 128 + kp * 4));
            *(uint32_t*)(sm + SM_AH + off) = *reinterpret_cast<uint32_t*>(&hv);
            *(uint32_t*)(sm + SM_AL + off) = *reinterpret_cast<uint32_t*>(&lv);
        }
        // ---- stage B (float4 copy of pre-swizzled fp16 image) ----
        {
            const float4* s1 = (const float4*)(wb + ch * 9216);
            float4* d1 = (float4*)(sm + SM_BH);
            for (int i = tid; i < 2304; i += 256) d1[i] = s1[i];
        }
        __syncthreads();
        hmma_chunk(sb, wm, wn, lane, acc);
    }

    hmma_epilogue(acc, row0, wm, wn, lane, bias, Cout, sStat, M);
    __syncthreads();
    for (int i = tid; i < 2 * HH; i += 256) atomicAdd(&g_stats[i], sStat[i]);
}

// ============================================================================
// Unified GEMM2 (in place): C[M,280] = relu(bn(C)) @ W[280,280] + b
// ============================================================================
__global__ void __launch_bounds__(256, 2)
gemm_inplace_mma(float* __restrict__ C, const uint32_t* __restrict__ wb,
                 const float* __restrict__ bias, int M) {
    extern __shared__ char sm[];
    uint32_t sb = smem_u32(sm);
    const int tid = threadIdx.x, wid = tid >> 5, lane = tid & 31;
    const int wm = wid >> 1, wn = wid & 1;
    const long row0 = (long)blockIdx.x * 64;
    float* sStat = (float*)(sm + SM_STAT);
    float* sSc = (float*)(sm + SM_SC);
    float* sSh = (float*)(sm + SM_SH);

    for (int i = tid; i < 2 * HH; i += 256) sStat[i] = 0.f;
    for (int i = tid; i < HH; i += 256) { sSc[i] = g_scale[i]; sSh[i] = g_shift[i]; }
    float acc[18][4];
#pragma unroll
    for (int nt = 0; nt < 18; nt++)
#pragma unroll
        for (int j = 0; j < 4; j++) acc[nt][j] = 0.f;
    __syncthreads();

    for (int ch = 0; ch < 5; ++ch) {
        if (ch) __syncthreads();
        const int kbase = ch * 64;
        for (int i = tid; i < 2048; i += 256) {
            int r = i >> 5, kp = i & 31;
            int c = kbase + 2 * kp;
            float2 v = make_float2(0.f, 0.f);
            if (c < HH) {
                long row = min(row0 + r, (long)M - 1);
                float2 y = *(const float2*)(C + row * HH + c);
                v.x = fmaxf(fmaf(y.x, sSc[c], sSh[c]), 0.f);
                v.y = fmaxf(fmaf(y.y, sSc[c + 1], sSh[c + 1]), 0.f);
            }
            __half2 hv = __floats2half2_rn(v.x, v.y);
            float2 hf = __half22float2(hv);
            __half2 lv = __floats2half2_rn(v.x - hf.x, v.y - hf.y);
            uint32_t off = SWZ((uint32_t)(r * 128 + kp * 4));
            *(uint32_t*)(sm + SM_AH + off) = *reinterpret_cast<uint32_t*>(&hv);
            *(uint32_t*)(sm + SM_AL + off) = *reinterpret_cast<uint32_t*>(&lv);
        }
        {
            const float4* s1 = (const float4*)(wb + ch * 9216);
            float4* d1 = (float4*)(sm + SM_BH);
            for (int i = tid; i < 2304; i += 256) d1[i] = s1[i];
        }
        __syncthreads();
        hmma_chunk(sb, wm, wn, lane, acc);
    }

    hmma_epilogue(acc, row0, wm, wn, lane, bias, C, sStat, M);
    __syncthreads();
    for (int i = tid; i < 2 * HH; i += 256) atomicAdd(&g_stats[i], sStat[i]);
}

// ---------------- finalize BN stats -> scale/shift; self-zero ----------------
__global__ void finalize_stats(const float* __restrict__ g, const float* __restrict__ be,
                               float invM) {
    int c = threadIdx.x;
    if (c >= HH) return;
    float s = g_stats[c];
    float s2 = g_stats[HH + c];
    g_stats[c] = 0.f;
    g_stats[HH + c] = 0.f;
    float mean = s * invM;
    float var = s2 * invM - mean * mean;
    float rstd = rsqrtf(var + 1e-5f);
    float sc = g[c] * rstd;
    g_scale[c] = sc;
    g_shift[c] = fmaf(-mean, sc, be[c]);
}

// ---------------- scatter: agg[dst[e]] += relu(bn(Y[e])) ----------------
__global__ void scatter_bn_relu(const float* __restrict__ Y, const int* __restrict__ dst,
                                float* __restrict__ agg) {
    long i = (long)blockIdx.x * 256 + threadIdx.x;
    if (i >= (long)EE * (HH / 4)) return;
    int e = (int)(i / (HH / 4));
    int c = (int)(i - (long)e * (HH / 4)) * 4;
    float4 y = *reinterpret_cast<const float4*>(Y + (long)e * HH + c);
    float* p = agg + (long)dst[e] * HH + c;
    float v0 = fmaf(y.x, g_scale[c + 0], g_shift[c + 0]);
    float v1 = fmaf(y.y, g_scale[c + 1], g_shift[c + 1]);
    float v2 = fmaf(y.z, g_scale[c + 2], g_shift[c + 2]);
    float v3 = fmaf(y.w, g_scale[c + 3], g_shift[c + 3]);
    if (v0 > 0.f) atomicAdd(p + 0, v0);
    if (v1 > 0.f) atomicAdd(p + 1, v1);
    if (v2 > 0.f) atomicAdd(p + 2, v2);
    if (v3 > 0.f) atomicAdd(p + 3, v3);
}

// ---------------- residual: h += relu(bn(U)) ----------------
__global__ void residual_bn_relu(const float* __restrict__ U, float* __restrict__ h) {
    int i = blockIdx.x * 256 + threadIdx.x;
    if (i >= NN * HH / 4) return;
    int c = (i % (HH / 4)) * 4;
    float4 u = *reinterpret_cast<const float4*>(U + (long)i * 4);
    float4 hv = *reinterpret_cast<float4*>(h + (long)i * 4);
    hv.x += fmaxf(fmaf(u.x, g_scale[c + 0], g_shift[c + 0]), 0.f);
    hv.y += fmaxf(fmaf(u.y, g_scale[c + 1], g_shift[c + 1]), 0.f);
    hv.z += fmaxf(fmaf(u.z, g_scale[c + 2], g_shift[c + 2]), 0.f);
    hv.w += fmaxf(fmaf(u.w, g_scale[c + 3], g_shift[c + 3]), 0.f);
    *reinterpret_cast<float4*>(h + (long)i * 4) = hv;
}

// ---------------- pooling + head ----------------
__global__ void pool_accum(const float* __restrict__ h, const int* __restrict__ batch,
                           float* __restrict__ pool) {
    int i = blockIdx.x * 256 + threadIdx.x;
    if (i >= NN * HH / 4) return;
    int n = i / (HH / 4);
    int c = (i - n * (HH / 4)) * 4;
    float4 v = *reinterpret_cast<const float4*>(h + (long)i * 4);
    float* p = pool + (long)batch[n] * HH + c;
    atomicAdd(p + 0, v.x);
    atomicAdd(p + 1, v.y);
    atomicAdd(p + 2, v.z);
    atomicAdd(p + 3, v.w);
}

__global__ void pool_count(const int* __restrict__ batch, float* __restrict__ cnt) {
    int n = blockIdx.x * 256 + threadIdx.x;
    if (n < NN) atomicAdd(&cnt[batch[n]], 1.0f);
}

__global__ void head_kernel(const float* __restrict__ pool, const float* __restrict__ cnt,
                            const float* __restrict__ Wmu, const float* __restrict__ bmu,
                            float* __restrict__ out) {
    int gph = blockIdx.x;
    int z = threadIdx.x;
    float inv = 1.0f / fmaxf(cnt[gph], 1.0f);
    float s = bmu[z];
    for (int k = 0; k < HH; k++) s = fmaf(pool[gph * HH + k] * inv, Wmu[k * ZZ + z], s);
    out[gph * ZZ + z] = s;
}

// ---------------- host orchestration ----------------
extern "C" void kernel_launch(void* const* d_in, const int* in_sizes, int n_in,
                              void* d_out, int out_size) {
    const float *x, *edge_attr, *Wi, *bi, *Wm1, *bm1, *g1, *be1, *Wm2, *bm2, *g2, *be2;
    const float *Wu1, *bu1, *g3, *be3, *Wu2, *bu2, *g4, *be4, *Wmu, *bmu;
    const int *edge_index, *batch;

    if (in_sizes[2] == 2 * EE) {
        x = (const float*)d_in[0];   edge_attr = (const float*)d_in[1];
        edge_index = (const int*)d_in[2]; batch = (const int*)d_in[3];
        Wi = (const float*)d_in[4];  bi = (const float*)d_in[5];
        Wm1 = (const float*)d_in[6]; bm1 = (const float*)d_in[7];
        g1 = (const float*)d_in[8];  be1 = (const float*)d_in[9];
        Wm2 = (const float*)d_in[10]; bm2 = (const float*)d_in[11];
        g2 = (const float*)d_in[12]; be2 = (const float*)d_in[13];
        Wu1 = (const float*)d_in[14]; bu1 = (const float*)d_in[15];
        g3 = (const float*)d_in[16]; be3 = (const float*)d_in[17];
        Wu2 = (const float*)d_in[18]; bu2 = (const float*)d_in[19];
        g4 = (const float*)d_in[20]; be4 = (const float*)d_in[21];
        Wmu = (const float*)d_in[22]; bmu = (const float*)d_in[23];
    } else {
        x = (const float*)d_in[0];   edge_attr = (const float*)d_in[1];
        Wi = (const float*)d_in[2];  bi = (const float*)d_in[3];
        Wm1 = (const float*)d_in[4]; bm1 = (const float*)d_in[5];
        g1 = (const float*)d_in[6];  be1 = (const float*)d_in[7];
        Wm2 = (const float*)d_in[8]; bm2 = (const float*)d_in[9];
        g2 = (const float*)d_in[10]; be2 = (const float*)d_in[11];
        Wu1 = (const float*)d_in[12]; bu1 = (const float*)d_in[13];
        g3 = (const float*)d_in[14]; be3 = (const float*)d_in[15];
        Wu2 = (const float*)d_in[16]; bu2 = (const float*)d_in[17];
        g4 = (const float*)d_in[18]; be4 = (const float*)d_in[19];
        Wmu = (const float*)d_in[20]; bmu = (const float*)d_in[21];
        edge_index = (const int*)d_in[22]; batch = (const int*)d_in[23];
    }
    const int* src = edge_index;
    const int* dst = edge_index + EE;

    float *hbuf, *Ybuf, *aggbuf, *Ubuf, *poolbuf, *cntbuf, *statsbuf;
    uint32_t *wb;
    cudaGetSymbolAddress((void**)&hbuf, g_h);
    cudaGetSymbolAddress((void**)&Ybuf, g_Y);
    cudaGetSymbolAddress((void**)&aggbuf, g_agg);
    cudaGetSymbolAddress((void**)&Ubuf, g_U);
    cudaGetSymbolAddress((void**)&poolbuf, g_pool);
    cudaGetSymbolAddress((void**)&cntbuf, g_cnt);
    cudaGetSymbolAddress((void**)&statsbuf, g_stats);
    cudaGetSymbolAddress((void**)&wb, g_wb);

    cudaFuncSetAttribute(gemm_cat_mma, cudaFuncAttributeMaxDynamicSharedMemorySize, SM_TOT);
    cudaFuncSetAttribute(gemm_inplace_mma, cudaFuncAttributeMaxDynamicSharedMemorySize, SM_TOT);

    const int NH_BLKS = (NN * HH + 255) / 256;
    const int NH4_BLKS = (NN * HH / 4 + 255) / 256;
    const int MSG_BLKS = EE / 64;                     // 5000
    const int UPD_BLKS = (NN + 63) / 64;              // 313
    const long EH4 = (long)EE * (HH / 4);
    const int SC_BLKS = (int)((EH4 + 255) / 256);

    zero4_kernel<<<1, 256>>>((float4*)statsbuf, 2 * HH / 4);
    input_layer<<<NH_BLKS, 256>>>(x, Wi, bi, hbuf);

    // ---- pre-convert ALL weight images (removes in-loop serialization) ----
    for (int l = 0; l < LL; l++) {
        uint32_t* base = wb + (long)l * 28 * 9216;
        conv_w<<<(9 * 9216) / 256, 256>>>(Wm1 + (long)l * K_MSG * HH, K_MSG, 9, base);
        conv_w<<<(5 * 9216) / 256, 256>>>(Wm2 + (long)l * HH * HH, HH, 5, base + 9 * 9216);
        conv_w<<<(9 * 9216) / 256, 256>>>(Wu1 + (long)l * K_UPD * HH, K_UPD, 9, base + 14 * 9216);
        conv_w<<<(5 * 9216) / 256, 256>>>(Wu2 + (long)l * HH * HH, HH, 5, base + 23 * 9216);
    }

    for (int l = 0; l < LL; l++) {
        uint32_t* wbase = wb + (long)l * 28 * 9216;

        // ---- message MLP on edges (HMMA fp16) ----
        gemm_cat_mma<<<MSG_BLKS, 256, SM_TOT>>>(hbuf, dst, hbuf, src, edge_attr,
                                                wbase, bm1 + l * HH, Ybuf, EE, K_MSG, 9);
        finalize_stats<<<1, 288>>>(g1 + l * HH, be1 + l * HH, 1.0f / EE);
        gemm_inplace_mma<<<MSG_BLKS, 256, SM_TOT>>>(Ybuf, wbase + 9 * 9216, bm2 + l * HH, EE);
        finalize_stats<<<1, 288>>>(g2 + l * HH, be2 + l * HH, 1.0f / EE);

        // ---- aggregate ----
        zero4_kernel<<<NH4_BLKS, 256>>>((float4*)aggbuf, NN * HH / 4);
        scatter_bn_relu<<<SC_BLKS, 256>>>(Ybuf, dst, aggbuf);

        // ---- update MLP on nodes (HMMA fp16, identity gather) ----
        gemm_cat_mma<<<UPD_BLKS, 256, SM_TOT>>>(hbuf, nullptr, aggbuf, nullptr, nullptr,
                                                wbase + 14 * 9216, bu1 + l * HH, Ubuf, NN, K_UPD, 9);
        finalize_stats<<<1, 288>>>(g3 + l * HH, be3 + l * HH, 1.0f / NN);
        gemm_inplace_mma<<<UPD_BLKS, 256, SM_TOT>>>(Ubuf, wbase + 23 * 9216, bu2 + l * HH, NN);
        finalize_stats<<<1, 288>>>(g4 + l * HH, be4 + l * HH, 1.0f / NN);
        residual_bn_relu<<<NH4_BLKS, 256>>>(Ubuf, hbuf);
    }

    zero4_kernel<<<(GG * HH / 4 + 255) / 256, 256>>>((float4*)poolbuf, GG * HH / 4);
    zero4_kernel<<<1, 256>>>((float4*)cntbuf, GG / 4);
    pool_accum<<<NH4_BLKS, 256>>>(hbuf, batch, poolbuf);
    pool_count<<<(NN + 255) / 256, 256>>>(batch, cntbuf);
    head_kernel<<<GG, ZZ>>>(poolbuf, cntbuf, Wmu, bmu, (float*)d_out);
}

// round 13
// speedup vs baseline: 2.0887x; 1.4200x over previous
#include <cuda_runtime.h>
#include <cuda_fp16.h>
#include <cstdint>

#define NN 20000
#define EE 320000
#define HH 280
#define GG 64
#define NFF 5
#define EFF 4
#define LL 3
#define ZZ 64
#define K_MSG 564   // 2H + EF
#define K_UPD 560   // 2H

// ---------------- scratch (static device globals; no runtime alloc) ----------------
__device__ float g_h[NN * HH];
__device__ float g_Y[EE * HH];
__device__ float g_agg[NN * HH];      // doubles as P2 during message phase
__device__ float g_U[NN * HH];        // doubles as P1 during message phase
__device__ float g_stats[2 * HH];
__device__ float g_scale[HH];
__device__ float g_shift[HH];
__device__ float g_pool[GG * HH];
__device__ float g_cnt[GG];
__device__ float g_zb[HH];            // zero bias
// pre-converted W images: per layer [wm1a:5][wm1b:5][wm2:5][wu1:9][wu2:5] = 29 chunks
__device__ uint32_t g_wb[LL * 29 * 9216];

// ================= helpers =================
__device__ __forceinline__ uint32_t smem_u32(const void* p) {
    uint32_t a;
    asm("{ .reg .u64 t; cvta.to.shared.u64 t, %1; cvt.u32.u64 %0, t; }" : "=r"(a) : "l"(p));
    return a;
}
#define SWZ(o) ((o) ^ (((o) >> 3) & 0x70))

__device__ __forceinline__ void ldsm_x4(uint32_t* r, uint32_t addr) {
    asm volatile("ldmatrix.sync.aligned.m8n8.x4.shared.b16 {%0,%1,%2,%3}, [%4];"
                 : "=r"(r[0]), "=r"(r[1]), "=r"(r[2]), "=r"(r[3]) : "r"(addr));
}
__device__ __forceinline__ void mma_f16(float* d, const uint32_t* a, uint32_t b0, uint32_t b1) {
    asm volatile("mma.sync.aligned.m16n8k16.row.col.f32.f16.f16.f32 "
                 "{%0,%1,%2,%3}, {%4,%5,%6,%7}, {%8,%9}, {%0,%1,%2,%3};"
                 : "+f"(d[0]), "+f"(d[1]), "+f"(d[2]), "+f"(d[3])
                 : "r"(a[0]), "r"(a[1]), "r"(a[2]), "r"(a[3]), "r"(b0), "r"(b1));
}

// smem layout (bytes) — 64-row A tile, total 60KB -> 2 blocks/SM
#define SM_STAT  0         // 560 floats (2240B)
#define SM_I0    2304      // 64 ints
#define SM_I1    2560
#define SM_SC    2816      // 280 floats
#define SM_SH    3936
#define SM_AH    8192      // 64x64 fp16 swizzled (8KB)
#define SM_AL    16384     // 8KB
#define SM_BH    24576     // 288x64 fp16 swizzled (36KB)
#define SM_TOT   61440

// ---------------- misc kernels ----------------
__global__ void zero4_kernel(float4* __restrict__ p, int n4) {
    int i = blockIdx.x * 256 + threadIdx.x;
    if (i < n4) p[i] = make_float4(0.f, 0.f, 0.f, 0.f);
}

__global__ void input_layer(const float* __restrict__ x, const float* __restrict__ Wi,
                            const float* __restrict__ bi, float* __restrict__ h) {
    int idx = blockIdx.x * 256 + threadIdx.x;
    if (idx >= NN * HH) return;
    int n = idx / HH;
    int c = idx - n * HH;
    float s = bi[c];
#pragma unroll
    for (int f = 0; f < NFF; f++) s = fmaf(x[n * NFF + f], Wi[f * HH + c], s);
    h[idx] = s;
}

// ---------------- W pre-conversion: fp32 [K,280] -> swizzled fp16 chunk image ----
__global__ void conv_w(const float* __restrict__ W, int K, int nCh,
                       uint32_t* __restrict__ ob) {
    int i = blockIdx.x * 256 + threadIdx.x;
    if (i >= nCh * 9216) return;
    int ch = i / 9216;
    int rem = i - ch * 9216;
    int kp = rem / 288;          // 0..31 (pair of k)
    int n = rem - kp * 288;      // 0..287
    int k0 = ch * 64 + 2 * kp;
    float v0 = (k0 < K && n < HH) ? W[(long)k0 * HH + n] : 0.f;
    float v1 = (k0 + 1 < K && n < HH) ? W[(long)(k0 + 1) * HH + n] : 0.f;
    __half2 hv = __floats2half2_rn(v0, v1);
    uint32_t off = SWZ((uint32_t)(n * 128 + kp * 4));
    ob[ch * 9216 + (off >> 2)] = *reinterpret_cast<uint32_t*>(&hv);
}

// ============================================================================
// HMMA compute core: one 64-k chunk, warp tile 16 rows x 144 cols, fp16
// 2-product split (A_hi*B + A_lo*B). 8 warps: wm 0..3 (rows), wn 0..1 (cols).
// ============================================================================
__device__ __forceinline__ void hmma_chunk(uint32_t sb, int wm, int wn,
                                           int lane, float acc[18][4]) {
    const uint32_t abase = sb + SM_AH;
    const uint32_t bbase = sb + SM_BH;
#pragma unroll
    for (int ks = 0; ks < 4; ks++) {
        uint32_t ah[4], al[4];
        {
            int row = wm * 16 + (lane & 15);
            int koff = ks * 32 + ((lane >> 4) << 4);
            uint32_t o = SWZ((uint32_t)(row * 128 + koff));
            ldsm_x4(ah, abase + o);
            ldsm_x4(al, abase + 8192 + o);
        }
        int bkoff = ks * 32 + ((lane >> 3) & 1) * 16;
        int bn0 = wn * 144 + ((lane >> 4) << 3) + (lane & 7);
#pragma unroll
        for (int g = 0; g < 5; g++) {
            const int nta = 2 * g, ntb = 2 * g + 1;
            uint32_t ba[4], bb[4];
            ldsm_x4(ba, bbase + SWZ((uint32_t)((bn0 + nta * 16) * 128 + bkoff)));
            if (g < 4) ldsm_x4(bb, bbase + SWZ((uint32_t)((bn0 + ntb * 16) * 128 + bkoff)));
#pragma unroll
            for (int p = 0; p < 2; p++)
                mma_f16(acc[nta * 2 + p], ah, ba[2 * p], ba[2 * p + 1]);
            if (g < 4) {
#pragma unroll
                for (int p = 0; p < 2; p++)
                    mma_f16(acc[ntb * 2 + p], ah, bb[2 * p], bb[2 * p + 1]);
            }
#pragma unroll
            for (int p = 0; p < 2; p++)
                mma_f16(acc[nta * 2 + p], al, ba[2 * p], ba[2 * p + 1]);
            if (g < 4) {
#pragma unroll
                for (int p = 0; p < 2; p++)
                    mma_f16(acc[ntb * 2 + p], al, bb[2 * p], bb[2 * p + 1]);
            }
        }
    }
}

// Epilogue: bias + guarded store + optional fused BN stats.
__device__ __forceinline__ void hmma_epilogue(float acc[18][4], long row0, int wm, int wn,
                                              int lane, const float* __restrict__ bias,
                                              float* __restrict__ Cout, float* sStat, int M,
                                              int doStat) {
    int rbase = wm * 16 + (lane >> 2);
    int cbase = wn * 144 + (lane & 3) * 2;
    long r1 = row0 + rbase;
    long r2 = r1 + 8;
    bool ok1 = r1 < M, ok2 = r2 < M;
#pragma unroll
    for (int nt = 0; nt < 18; nt++) {
        int c = cbase + nt * 8;
        if (c < HH) {
            float b0 = bias[c], b1 = bias[c + 1];
            float v0 = acc[nt][0] + b0;
            float v1 = acc[nt][1] + b1;
            float v2 = acc[nt][2] + b0;
            float v3 = acc[nt][3] + b1;
            float s0 = 0.f, s1 = 0.f, q0 = 0.f, q1 = 0.f;
            if (ok1) {
                *reinterpret_cast<float2*>(Cout + r1 * HH + c) = make_float2(v0, v1);
                s0 += v0; s1 += v1; q0 += v0 * v0; q1 += v1 * v1;
            }
            if (ok2) {
                *reinterpret_cast<float2*>(Cout + r2 * HH + c) = make_float2(v2, v3);
                s0 += v2; s1 += v3; q0 += v2 * v2; q1 += v3 * v3;
            }
            if (doStat && (ok1 || ok2)) {
                atomicAdd(&sStat[c], s0);
                atomicAdd(&sStat[c + 1], s1);
                atomicAdd(&sStat[HH + c], q0);
                atomicAdd(&sStat[HH + c + 1], q1);
            }
        }
    }
}

// ============================================================================
// Unified GEMM1: C[M,280] = cat(A0[idx0], A1[idx1], ea?) @ W[K,280] + b
// 64 rows per block, 256 threads, 2 blocks/SM.
// ============================================================================
__global__ void __launch_bounds__(256, 2)
gemm_cat_mma(const float* __restrict__ A0, const int* __restrict__ idx0,
             const float* __restrict__ A1, const int* __restrict__ idx1,
             const float* __restrict__ ea,
             const uint32_t* __restrict__ wb,
             const float* __restrict__ bias, float* __restrict__ Cout,
             int M, int K, int nCh, int doStat) {
    extern __shared__ char sm[];
    uint32_t sb = smem_u32(sm);
    const int tid = threadIdx.x, wid = tid >> 5, lane = tid & 31;
    const int wm = wid >> 1, wn = wid & 1;
    const long row0 = (long)blockIdx.x * 64;
    int* sI0 = (int*)(sm + SM_I0);
    int* sI1 = (int*)(sm + SM_I1);
    float* sStat = (float*)(sm + SM_STAT);

    for (int i = tid; i < 2 * HH; i += 256) sStat[i] = 0.f;
    if (tid < 64) {
        int e = (int)min(row0 + tid, (long)M - 1);
        sI0[tid] = idx0 ? idx0[e] : e;
        sI1[tid] = idx1 ? idx1[e] : e;
    }
    float acc[18][4];
#pragma unroll
    for (int nt = 0; nt < 18; nt++)
#pragma unroll
        for (int j = 0; j < 4; j++) acc[nt][j] = 0.f;
    __syncthreads();

    for (int ch = 0; ch < nCh; ++ch) {
        if (ch) __syncthreads();
        const int kbase = ch * 64;
        // ---- stage A (gathered, fp32 -> hi/lo fp16, swizzled): 64x32 float2 ----
        for (int i = tid; i < 2048; i += 256) {
            int r = i >> 5, kp = i & 31;
            int c = kbase + 2 * kp;
            float2 v = make_float2(0.f, 0.f);
            if (c < K) {
                if (c < HH)          v = *(const float2*)(A0 + (long)sI0[r] * HH + c);
                else if (c < 2 * HH) v = *(const float2*)(A1 + (long)sI1[r] * HH + (c - HH));
                else                 v = *(const float2*)(ea + (row0 + r) * EFF + (c - 2 * HH));
            }
            __half2 hv = __floats2half2_rn(v.x, v.y);
            float2 hf = __half22float2(hv);
            __half2 lv = __floats2half2_rn(v.x - hf.x, v.y - hf.y);
            uint32_t off = SWZ((uint32_t)(r * 128 + kp * 4));
            *(uint32_t*)(sm + SM_AH + off) = *reinterpret_cast<uint32_t*>(&hv);
            *(uint32_t*)(sm + SM_AL + off) = *reinterpret_cast<uint32_t*>(&lv);
        }
        // ---- stage B (float4 copy of pre-swizzled fp16 image) ----
        {
            const float4* s1 = (const float4*)(wb + ch * 9216);
            float4* d1 = (float4*)(sm + SM_BH);
            for (int i = tid; i < 2304; i += 256) d1[i] = s1[i];
        }
        __syncthreads();
        hmma_chunk(sb, wm, wn, lane, acc);
    }

    hmma_epilogue(acc, row0, wm, wn, lane, bias, Cout, sStat, M, doStat);
    if (doStat) {
        __syncthreads();
        for (int i = tid; i < 2 * HH; i += 256) atomicAdd(&g_stats[i], sStat[i]);
    }
}

// ============================================================================
// Unified GEMM2 (in place): C[M,280] = relu(bn(C)) @ W[280,280] + b
// ============================================================================
__global__ void __launch_bounds__(256, 2)
gemm_inplace_mma(float* __restrict__ C, const uint32_t* __restrict__ wb,
                 const float* __restrict__ bias, int M) {
    extern __shared__ char sm[];
    uint32_t sb = smem_u32(sm);
    const int tid = threadIdx.x, wid = tid >> 5, lane = tid & 31;
    const int wm = wid >> 1, wn = wid & 1;
    const long row0 = (long)blockIdx.x * 64;
    float* sStat = (float*)(sm + SM_STAT);
    float* sSc = (float*)(sm + SM_SC);
    float* sSh = (float*)(sm + SM_SH);

    for (int i = tid; i < 2 * HH; i += 256) sStat[i] = 0.f;
    for (int i = tid; i < HH; i += 256) { sSc[i] = g_scale[i]; sSh[i] = g_shift[i]; }
    float acc[18][4];
#pragma unroll
    for (int nt = 0; nt < 18; nt++)
#pragma unroll
        for (int j = 0; j < 4; j++) acc[nt][j] = 0.f;
    __syncthreads();

    for (int ch = 0; ch < 5; ++ch) {
        if (ch) __syncthreads();
        const int kbase = ch * 64;
        for (int i = tid; i < 2048; i += 256) {
            int r = i >> 5, kp = i & 31;
            int c = kbase + 2 * kp;
            float2 v = make_float2(0.f, 0.f);
            if (c < HH) {
                long row = min(row0 + r, (long)M - 1);
                float2 y = *(const float2*)(C + row * HH + c);
                v.x = fmaxf(fmaf(y.x, sSc[c], sSh[c]), 0.f);
                v.y = fmaxf(fmaf(y.y, sSc[c + 1], sSh[c + 1]), 0.f);
            }
            __half2 hv = __floats2half2_rn(v.x, v.y);
            float2 hf = __half22float2(hv);
            __half2 lv = __floats2half2_rn(v.x - hf.x, v.y - hf.y);
            uint32_t off = SWZ((uint32_t)(r * 128 + kp * 4));
            *(uint32_t*)(sm + SM_AH + off) = *reinterpret_cast<uint32_t*>(&hv);
            *(uint32_t*)(sm + SM_AL + off) = *reinterpret_cast<uint32_t*>(&lv);
        }
        {
            const float4* s1 = (const float4*)(wb + ch * 9216);
            float4* d1 = (float4*)(sm + SM_BH);
            for (int i = tid; i < 2304; i += 256) d1[i] = s1[i];
        }
        __syncthreads();
        hmma_chunk(sb, wm, wn, lane, acc);
    }

    hmma_epilogue(acc, row0, wm, wn, lane, bias, C, sStat, M, 1);
    __syncthreads();
    for (int i = tid; i < 2 * HH; i += 256) atomicAdd(&g_stats[i], sStat[i]);
}

// ============================================================================
// Combine: Y[e] = P1[dst[e]] + P2[src[e]] + ea[e]@W1c + bias, fused BN stats.
// 32 edges per block. P1/P2 are L2-resident (22MB each).
// ============================================================================
__global__ void __launch_bounds__(256)
combine_msg(const float* __restrict__ P1, const float* __restrict__ P2,
            const float* __restrict__ ea,
            const int* __restrict__ dst, const int* __restrict__ src,
            const float* __restrict__ W1c,   // rows 560..563 of Wm1: [4*HH] linear
            const float* __restrict__ bias, float* __restrict__ Y) {
    __shared__ float sStat[2 * HH];
    __shared__ float sW[EFF * HH];
    __shared__ float sB[HH];
    __shared__ int sD[32], sS[32];
    __shared__ float4 sEv[32];
    const int tid = threadIdx.x;
    const long e0 = (long)blockIdx.x * 32;

    for (int i = tid; i < 2 * HH; i += 256) sStat[i] = 0.f;
    for (int i = tid; i < EFF * HH; i += 256) sW[i] = W1c[i];
    for (int i = tid; i < HH; i += 256) sB[i] = bias[i];
    if (tid < 32) {
        long e = e0 + tid;
        sD[tid] = dst[e];
        sS[tid] = src[e];
        sEv[tid] = *(const float4*)(ea + e * EFF);
    }
    __syncthreads();

    for (int it = tid; it < 32 * 70; it += 256) {
        int er = it / 70, c4 = it - er * 70;
        int c = c4 * 4;
        long e = e0 + er;
        float4 a = *(const float4*)(P1 + (long)sD[er] * HH + c);
        float4 b = *(const float4*)(P2 + (long)sS[er] * HH + c);
        float4 ev = sEv[er];
        float4 v;
        v.x = a.x + b.x + sB[c + 0] + ev.x * sW[c + 0] + ev.y * sW[HH + c + 0] + ev.z * sW[2 * HH + c + 0] + ev.w * sW[3 * HH + c + 0];
        v.y = a.y + b.y + sB[c + 1] + ev.x * sW[c + 1] + ev.y * sW[HH + c + 1] + ev.z * sW[2 * HH + c + 1] + ev.w * sW[3 * HH + c + 1];
        v.z = a.z + b.z + sB[c + 2] + ev.x * sW[c + 2] + ev.y * sW[HH + c + 2] + ev.z * sW[2 * HH + c + 2] + ev.w * sW[3 * HH + c + 2];
        v.w = a.w + b.w + sB[c + 3] + ev.x * sW[c + 3] + ev.y * sW[HH + c + 3] + ev.z * sW[2 * HH + c + 3] + ev.w * sW[3 * HH + c + 3];
        *(float4*)(Y + e * HH + c) = v;
        atomicAdd(&sStat[c + 0], v.x);
        atomicAdd(&sStat[c + 1], v.y);
        atomicAdd(&sStat[c + 2], v.z);
        atomicAdd(&sStat[c + 3], v.w);
        atomicAdd(&sStat[HH + c + 0], v.x * v.x);
        atomicAdd(&sStat[HH + c + 1], v.y * v.y);
        atomicAdd(&sStat[HH + c + 2], v.z * v.z);
        atomicAdd(&sStat[HH + c + 3], v.w * v.w);
    }
    __syncthreads();
    for (int i = tid; i < 2 * HH; i += 256) atomicAdd(&g_stats[i], sStat[i]);
}

// ---------------- finalize BN stats -> scale/shift; self-zero ----------------
__global__ void finalize_stats(const float* __restrict__ g, const float* __restrict__ be,
                               float invM) {
    int c = threadIdx.x;
    if (c >= HH) return;
    float s = g_stats[c];
    float s2 = g_stats[HH + c];
    g_stats[c] = 0.f;
    g_stats[HH + c] = 0.f;
    float mean = s * invM;
    float var = s2 * invM - mean * mean;
    float rstd = rsqrtf(var + 1e-5f);
    float sc = g[c] * rstd;
    g_scale[c] = sc;
    g_shift[c] = fmaf(-mean, sc, be[c]);
}

// ---------------- scatter: agg[dst[e]] += relu(bn(Y[e])) ----------------
__global__ void scatter_bn_relu(const float* __restrict__ Y, const int* __restrict__ dst,
                                float* __restrict__ agg) {
    long i = (long)blockIdx.x * 256 + threadIdx.x;
    if (i >= (long)EE * (HH / 4)) return;
    int e = (int)(i / (HH / 4));
    int c = (int)(i - (long)e * (HH / 4)) * 4;
    float4 y = *reinterpret_cast<const float4*>(Y + (long)e * HH + c);
    float* p = agg + (long)dst[e] * HH + c;
    float v0 = fmaf(y.x, g_scale[c + 0], g_shift[c + 0]);
    float v1 = fmaf(y.y, g_scale[c + 1], g_shift[c + 1]);
    float v2 = fmaf(y.z, g_scale[c + 2], g_shift[c + 2]);
    float v3 = fmaf(y.w, g_scale[c + 3], g_shift[c + 3]);
    if (v0 > 0.f) atomicAdd(p + 0, v0);
    if (v1 > 0.f) atomicAdd(p + 1, v1);
    if (v2 > 0.f) atomicAdd(p + 2, v2);
    if (v3 > 0.f) atomicAdd(p + 3, v3);
}

// ---------------- residual: h += relu(bn(U)) ----------------
__global__ void residual_bn_relu(const float* __restrict__ U, float* __restrict__ h) {
    int i = blockIdx.x * 256 + threadIdx.x;
    if (i >= NN * HH / 4) return;
    int c = (i % (HH / 4)) * 4;
    float4 u = *reinterpret_cast<const float4*>(U + (long)i * 4);
    float4 hv = *reinterpret_cast<float4*>(h + (long)i * 4);
    hv.x += fmaxf(fmaf(u.x, g_scale[c + 0], g_shift[c + 0]), 0.f);
    hv.y += fmaxf(fmaf(u.y, g_scale[c + 1], g_shift[c + 1]), 0.f);
    hv.z += fmaxf(fmaf(u.z, g_scale[c + 2], g_shift[c + 2]), 0.f);
    hv.w += fmaxf(fmaf(u.w, g_scale[c + 3], g_shift[c + 3]), 0.f);
    *reinterpret_cast<float4*>(h + (long)i * 4) = hv;
}

// ---------------- pooling + head ----------------
__global__ void pool_accum(const float* __restrict__ h, const int* __restrict__ batch,
                           float* __restrict__ pool) {
    int i = blockIdx.x * 256 + threadIdx.x;
    if (i >= NN * HH / 4) return;
    int n = i / (HH / 4);
    int c = (i - n * (HH / 4)) * 4;
    float4 v = *reinterpret_cast<const float4*>(h + (long)i * 4);
    float* p = pool + (long)batch[n] * HH + c;
    atomicAdd(p + 0, v.x);
    atomicAdd(p + 1, v.y);
    atomicAdd(p + 2, v.z);
    atomicAdd(p + 3, v.w);
}

__global__ void pool_count(const int* __restrict__ batch, float* __restrict__ cnt) {
    int n = blockIdx.x * 256 + threadIdx.x;
    if (n < NN) atomicAdd(&cnt[batch[n]], 1.0f);
}

__global__ void head_kernel(const float* __restrict__ pool, const float* __restrict__ cnt,
                            const float* __restrict__ Wmu, const float* __restrict__ bmu,
                            float* __restrict__ out) {
    int gph = blockIdx.x;
    int z = threadIdx.x;
    float inv = 1.0f / fmaxf(cnt[gph], 1.0f);
    float s = bmu[z];
    for (int k = 0; k < HH; k++) s = fmaf(pool[gph * HH + k] * inv, Wmu[k * ZZ + z], s);
    out[gph * ZZ + z] = s;
}

// ---------------- host orchestration ----------------
extern "C" void kernel_launch(void* const* d_in, const int* in_sizes, int n_in,
                              void* d_out, int out_size) {
    const float *x, *edge_attr, *Wi, *bi, *Wm1, *bm1, *g1, *be1, *Wm2, *bm2, *g2, *be2;
    const float *Wu1, *bu1, *g3, *be3, *Wu2, *bu2, *g4, *be4, *Wmu, *bmu;
    const int *edge_index, *batch;

    if (in_sizes[2] == 2 * EE) {
        x = (const float*)d_in[0];   edge_attr = (const float*)d_in[1];
        edge_index = (const int*)d_in[2]; batch = (const int*)d_in[3];
        Wi = (const float*)d_in[4];  bi = (const float*)d_in[5];
        Wm1 = (const float*)d_in[6]; bm1 = (const float*)d_in[7];
        g1 = (const float*)d_in[8];  be1 = (const float*)d_in[9];
        Wm2 = (const float*)d_in[10]; bm2 = (const float*)d_in[11];
        g2 = (const float*)d_in[12]; be2 = (const float*)d_in[13];
        Wu1 = (const float*)d_in[14]; bu1 = (const float*)d_in[15];
        g3 = (const float*)d_in[16]; be3 = (const float*)d_in[17];
        Wu2 = (const float*)d_in[18]; bu2 = (const float*)d_in[19];
        g4 = (const float*)d_in[20]; be4 = (const float*)d_in[21];
        Wmu = (const float*)d_in[22]; bmu = (const float*)d_in[23];
    } else {
        x = (const float*)d_in[0];   edge_attr = (const float*)d_in[1];
        Wi = (const float*)d_in[2];  bi = (const float*)d_in[3];
        Wm1 = (const float*)d_in[4]; bm1 = (const float*)d_in[5];
        g1 = (const float*)d_in[6];  be1 = (const float*)d_in[7];
        Wm2 = (const float*)d_in[8]; bm2 = (const float*)d_in[9];
        g2 = (const float*)d_in[10]; be2 = (const float*)d_in[11];
        Wu1 = (const float*)d_in[12]; bu1 = (const float*)d_in[13];
        g3 = (const float*)d_in[14]; be3 = (const float*)d_in[15];
        Wu2 = (const float*)d_in[16]; bu2 = (const float*)d_in[17];
        g4 = (const float*)d_in[18]; be4 = (const float*)d_in[19];
        Wmu = (const float*)d_in[20]; bmu = (const float*)d_in[21];
        edge_index = (const int*)d_in[22]; batch = (const int*)d_in[23];
    }
    const int* src = edge_index;
    const int* dst = edge_index + EE;

    float *hbuf, *Ybuf, *aggbuf, *Ubuf, *poolbuf, *cntbuf, *statsbuf, *zbuf;
    uint32_t *wb;
    cudaGetSymbolAddress((void**)&hbuf, g_h);
    cudaGetSymbolAddress((void**)&Ybuf, g_Y);
    cudaGetSymbolAddress((void**)&aggbuf, g_agg);
    cudaGetSymbolAddress((void**)&Ubuf, g_U);
    cudaGetSymbolAddress((void**)&poolbuf, g_pool);
    cudaGetSymbolAddress((void**)&cntbuf, g_cnt);
    cudaGetSymbolAddress((void**)&statsbuf, g_stats);
    cudaGetSymbolAddress((void**)&zbuf, g_zb);
    cudaGetSymbolAddress((void**)&wb, g_wb);

    cudaFuncSetAttribute(gemm_cat_mma, cudaFuncAttributeMaxDynamicSharedMemorySize, SM_TOT);
    cudaFuncSetAttribute(gemm_inplace_mma, cudaFuncAttributeMaxDynamicSharedMemorySize, SM_TOT);

    const int NH_BLKS = (NN * HH + 255) / 256;
    const int NH4_BLKS = (NN * HH / 4 + 255) / 256;
    const int MSG_BLKS = EE / 64;                     // 5000
    const int UPD_BLKS = (NN + 63) / 64;              // 313
    const long EH4 = (long)EE * (HH / 4);
    const int SC_BLKS = (int)((EH4 + 255) / 256);

    zero4_kernel<<<1, 256>>>((float4*)statsbuf, 2 * HH / 4);
    zero4_kernel<<<1, 256>>>((float4*)zbuf, HH / 4);
    input_layer<<<NH_BLKS, 256>>>(x, Wi, bi, hbuf);

    // ---- pre-convert ALL weight images ----
    for (int l = 0; l < LL; l++) {
        uint32_t* base = wb + (long)l * 29 * 9216;
        const float* wm1 = Wm1 + (long)l * K_MSG * HH;
        conv_w<<<(5 * 9216) / 256, 256>>>(wm1, HH, 5, base);                       // W1a
        conv_w<<<(5 * 9216) / 256, 256>>>(wm1 + 280 * HH, HH, 5, base + 5 * 9216); // W1b
        conv_w<<<(5 * 9216) / 256, 256>>>(Wm2 + (long)l * HH * HH, HH, 5, base + 10 * 9216);
        conv_w<<<(9 * 9216) / 256, 256>>>(Wu1 + (long)l * K_UPD * HH, K_UPD, 9, base + 15 * 9216);
        conv_w<<<(5 * 9216) / 256, 256>>>(Wu2 + (long)l * HH * HH, HH, 5, base + 24 * 9216);
    }

    for (int l = 0; l < LL; l++) {
        uint32_t* wbase = wb + (long)l * 29 * 9216;
        const float* wm1 = Wm1 + (long)l * K_MSG * HH;

        // ---- message MLP layer 1, distributed: P1=h@W1a, P2=h@W1b, combine ----
        gemm_cat_mma<<<UPD_BLKS, 256, SM_TOT>>>(hbuf, nullptr, hbuf, nullptr, nullptr,
                                                wbase, zbuf, Ubuf /*P1*/, NN, HH, 5, 0);
        gemm_cat_mma<<<UPD_BLKS, 256, SM_TOT>>>(hbuf, nullptr, hbuf, nullptr, nullptr,
                                                wbase + 5 * 9216, zbuf, aggbuf /*P2*/, NN, HH, 5, 0);
        combine_msg<<<EE / 32, 256>>>(Ubuf, aggbuf, edge_attr, dst, src,
                                      wm1 + 560 * HH, bm1 + l * HH, Ybuf);
        finalize_stats<<<1, 288>>>(g1 + l * HH, be1 + l * HH, 1.0f / EE);
        gemm_inplace_mma<<<MSG_BLKS, 256, SM_TOT>>>(Ybuf, wbase + 10 * 9216, bm2 + l * HH, EE);
        finalize_stats<<<1, 288>>>(g2 + l * HH, be2 + l * HH, 1.0f / EE);

        // ---- aggregate ----
        zero4_kernel<<<NH4_BLKS, 256>>>((float4*)aggbuf, NN * HH / 4);
        scatter_bn_relu<<<SC_BLKS, 256>>>(Ybuf, dst, aggbuf);

        // ---- update MLP on nodes ----
        gemm_cat_mma<<<UPD_BLKS, 256, SM_TOT>>>(hbuf, nullptr, aggbuf, nullptr, nullptr,
                                                wbase + 15 * 9216, bu1 + l * HH, Ubuf, NN, K_UPD, 9, 1);
        finalize_stats<<<1, 288>>>(g3 + l * HH, be3 + l * HH, 1.0f / NN);
        gemm_inplace_mma<<<UPD_BLKS, 256, SM_TOT>>>(Ubuf, wbase + 24 * 9216, bu2 + l * HH, NN);
        finalize_stats<<<1, 288>>>(g4 + l * HH, be4 + l * HH, 1.0f / NN);
        residual_bn_relu<<<NH4_BLKS, 256>>>(Ubuf, hbuf);
    }

    zero4_kernel<<<(GG * HH / 4 + 255) / 256, 256>>>((float4*)poolbuf, GG * HH / 4);
    zero4_kernel<<<1, 256>>>((float4*)cntbuf, GG / 4);
    pool_accum<<<NH4_BLKS, 256>>>(hbuf, batch, poolbuf);
    pool_count<<<(NN + 255) / 256, 256>>>(batch, cntbuf);
    head_kernel<<<GG, ZZ>>>(poolbuf, cntbuf, Wmu, bmu, (float*)d_out);
}

// round 14
// speedup vs baseline: 2.4094x; 1.1535x over previous
#include <cuda_runtime.h>
#include <cuda_fp16.h>
#include <cstdint>

#define NN 20000
#define EE 320000
#define HH 280
#define GG 64
#define NFF 5
#define EFF 4
#define LL 3
#define ZZ 64
#define K_MSG 564   // 2H + EF
#define K_UPD 560   // 2H

// ---------------- scratch (static device globals; no runtime alloc) ----------------
__device__ float g_h[NN * HH];
__device__ float g_Y[EE * HH];
__device__ float g_agg[NN * HH];      // doubles as P2 during message phase
__device__ float g_U[NN * HH];        // doubles as P1 during message phase
__device__ float g_stats[2 * HH];
__device__ float g_scale[HH];
__device__ float g_shift[HH];
__device__ float g_pool[GG * HH];
__device__ float g_cnt[GG];
__device__ float g_zb[HH];            // zero bias
// pre-converted W images: per layer [wm1a:5][wm1b:5][wm2:5][wu1:9][wu2:5] = 29 chunks
__device__ uint32_t g_wb[LL * 29 * 9216];

// ================= helpers =================
__device__ __forceinline__ uint32_t smem_u32(const void* p) {
    uint32_t a;
    asm("{ .reg .u64 t; cvta.to.shared.u64 t, %1; cvt.u32.u64 %0, t; }" : "=r"(a) : "l"(p));
    return a;
}
#define SWZ(o) ((o) ^ (((o) >> 3) & 0x70))

__device__ __forceinline__ void ldsm_x4(uint32_t* r, uint32_t addr) {
    asm volatile("ldmatrix.sync.aligned.m8n8.x4.shared.b16 {%0,%1,%2,%3}, [%4];"
                 : "=r"(r[0]), "=r"(r[1]), "=r"(r[2]), "=r"(r[3]) : "r"(addr));
}
__device__ __forceinline__ void mma_f16(float* d, const uint32_t* a, uint32_t b0, uint32_t b1) {
    asm volatile("mma.sync.aligned.m16n8k16.row.col.f32.f16.f16.f32 "
                 "{%0,%1,%2,%3}, {%4,%5,%6,%7}, {%8,%9}, {%0,%1,%2,%3};"
                 : "+f"(d[0]), "+f"(d[1]), "+f"(d[2]), "+f"(d[3])
                 : "r"(a[0]), "r"(a[1]), "r"(a[2]), "r"(a[3]), "r"(b0), "r"(b1));
}

// smem layout (bytes) — 64-row A tile (hi only), total 52KB -> 3 blocks/SM
#define SM_STAT  0         // 560 floats (2240B)
#define SM_I0    2304      // 64 ints
#define SM_I1    2560
#define SM_SC    2816      // 280 floats
#define SM_SH    3936
#define SM_AH    8192      // 64x64 fp16 swizzled (8KB)
#define SM_BH    16384     // 288x64 fp16 swizzled (36KB)
#define SM_TOT   53248

// ---------------- misc kernels ----------------
__global__ void zero4_kernel(float4* __restrict__ p, int n4) {
    int i = blockIdx.x * 256 + threadIdx.x;
    if (i < n4) p[i] = make_float4(0.f, 0.f, 0.f, 0.f);
}

__global__ void input_layer(const float* __restrict__ x, const float* __restrict__ Wi,
                            const float* __restrict__ bi, float* __restrict__ h) {
    int idx = blockIdx.x * 256 + threadIdx.x;
    if (idx >= NN * HH) return;
    int n = idx / HH;
    int c = idx - n * HH;
    float s = bi[c];
#pragma unroll
    for (int f = 0; f < NFF; f++) s = fmaf(x[n * NFF + f], Wi[f * HH + c], s);
    h[idx] = s;
}

// ---------------- W pre-conversion: fp32 [K,280] -> swizzled fp16 chunk image ----
__global__ void conv_w(const float* __restrict__ W, int K, int nCh,
                       uint32_t* __restrict__ ob) {
    int i = blockIdx.x * 256 + threadIdx.x;
    if (i >= nCh * 9216) return;
    int ch = i / 9216;
    int rem = i - ch * 9216;
    int kp = rem / 288;          // 0..31 (pair of k)
    int n = rem - kp * 288;      // 0..287
    int k0 = ch * 64 + 2 * kp;
    float v0 = (k0 < K && n < HH) ? W[(long)k0 * HH + n] : 0.f;
    float v1 = (k0 + 1 < K && n < HH) ? W[(long)(k0 + 1) * HH + n] : 0.f;
    __half2 hv = __floats2half2_rn(v0, v1);
    uint32_t off = SWZ((uint32_t)(n * 128 + kp * 4));
    ob[ch * 9216 + (off >> 2)] = *reinterpret_cast<uint32_t*>(&hv);
}

// ============================================================================
// HMMA compute core: one 64-k chunk, warp tile 16 rows x 144 cols, single-fp16
// product. 8 warps: wm 0..3 (rows), wn 0..1 (cols).
// ============================================================================
__device__ __forceinline__ void hmma_chunk(uint32_t sb, int wm, int wn,
                                           int lane, float acc[18][4]) {
    const uint32_t abase = sb + SM_AH;
    const uint32_t bbase = sb + SM_BH;
#pragma unroll
    for (int ks = 0; ks < 4; ks++) {
        uint32_t ah[4];
        {
            int row = wm * 16 + (lane & 15);
            int koff = ks * 32 + ((lane >> 4) << 4);
            ldsm_x4(ah, abase + SWZ((uint32_t)(row * 128 + koff)));
        }
        int bkoff = ks * 32 + ((lane >> 3) & 1) * 16;
        int bn0 = wn * 144 + ((lane >> 4) << 3) + (lane & 7);
#pragma unroll
        for (int g = 0; g < 5; g++) {
            const int nta = 2 * g, ntb = 2 * g + 1;
            uint32_t ba[4], bb[4];
            ldsm_x4(ba, bbase + SWZ((uint32_t)((bn0 + nta * 16) * 128 + bkoff)));
            if (g < 4) ldsm_x4(bb, bbase + SWZ((uint32_t)((bn0 + ntb * 16) * 128 + bkoff)));
#pragma unroll
            for (int p = 0; p < 2; p++)
                mma_f16(acc[nta * 2 + p], ah, ba[2 * p], ba[2 * p + 1]);
            if (g < 4) {
#pragma unroll
                for (int p = 0; p < 2; p++)
                    mma_f16(acc[ntb * 2 + p], ah, bb[2 * p], bb[2 * p + 1]);
            }
        }
    }
}

// Epilogue: bias + guarded store + optional fused BN stats.
__device__ __forceinline__ void hmma_epilogue(float acc[18][4], long row0, int wm, int wn,
                                              int lane, const float* __restrict__ bias,
                                              float* __restrict__ Cout, float* sStat, int M,
                                              int doStat) {
    int rbase = wm * 16 + (lane >> 2);
    int cbase = wn * 144 + (lane & 3) * 2;
    long r1 = row0 + rbase;
    long r2 = r1 + 8;
    bool ok1 = r1 < M, ok2 = r2 < M;
#pragma unroll
    for (int nt = 0; nt < 18; nt++) {
        int c = cbase + nt * 8;
        if (c < HH) {
            float b0 = bias[c], b1 = bias[c + 1];
            float v0 = acc[nt][0] + b0;
            float v1 = acc[nt][1] + b1;
            float v2 = acc[nt][2] + b0;
            float v3 = acc[nt][3] + b1;
            float s0 = 0.f, s1 = 0.f, q0 = 0.f, q1 = 0.f;
            if (ok1) {
                *reinterpret_cast<float2*>(Cout + r1 * HH + c) = make_float2(v0, v1);
                s0 += v0; s1 += v1; q0 += v0 * v0; q1 += v1 * v1;
            }
            if (ok2) {
                *reinterpret_cast<float2*>(Cout + r2 * HH + c) = make_float2(v2, v3);
                s0 += v2; s1 += v3; q0 += v2 * v2; q1 += v3 * v3;
            }
            if (doStat && (ok1 || ok2)) {
                atomicAdd(&sStat[c], s0);
                atomicAdd(&sStat[c + 1], s1);
                atomicAdd(&sStat[HH + c], q0);
                atomicAdd(&sStat[HH + c + 1], q1);
            }
        }
    }
}

// ============================================================================
// Unified GEMM1: C[M,280] = cat(A0[idx0], A1[idx1], ea?) @ W[K,280] + b
// 64 rows per block, 256 threads, 3 blocks/SM.
// ============================================================================
__global__ void __launch_bounds__(256, 3)
gemm_cat_mma(const float* __restrict__ A0, const int* __restrict__ idx0,
             const float* __restrict__ A1, const int* __restrict__ idx1,
             const float* __restrict__ ea,
             const uint32_t* __restrict__ wb,
             const float* __restrict__ bias, float* __restrict__ Cout,
             int M, int K, int nCh, int doStat) {
    extern __shared__ char sm[];
    uint32_t sb = smem_u32(sm);
    const int tid = threadIdx.x, wid = tid >> 5, lane = tid & 31;
    const int wm = wid >> 1, wn = wid & 1;
    const long row0 = (long)blockIdx.x * 64;
    int* sI0 = (int*)(sm + SM_I0);
    int* sI1 = (int*)(sm + SM_I1);
    float* sStat = (float*)(sm + SM_STAT);

    for (int i = tid; i < 2 * HH; i += 256) sStat[i] = 0.f;
    if (tid < 64) {
        int e = (int)min(row0 + tid, (long)M - 1);
        sI0[tid] = idx0 ? idx0[e] : e;
        sI1[tid] = idx1 ? idx1[e] : e;
    }
    float acc[18][4];
#pragma unroll
    for (int nt = 0; nt < 18; nt++)
#pragma unroll
        for (int j = 0; j < 4; j++) acc[nt][j] = 0.f;
    __syncthreads();

    for (int ch = 0; ch < nCh; ++ch) {
        if (ch) __syncthreads();
        const int kbase = ch * 64;
        // ---- stage A (gathered, fp32 -> fp16, swizzled): 64x32 float2 ----
        for (int i = tid; i < 2048; i += 256) {
            int r = i >> 5, kp = i & 31;
            int c = kbase + 2 * kp;
            float2 v = make_float2(0.f, 0.f);
            if (c < K) {
                if (c < HH)          v = *(const float2*)(A0 + (long)sI0[r] * HH + c);
                else if (c < 2 * HH) v = *(const float2*)(A1 + (long)sI1[r] * HH + (c - HH));
                else                 v = *(const float2*)(ea + (row0 + r) * EFF + (c - 2 * HH));
            }
            __half2 hv = __floats2half2_rn(v.x, v.y);
            uint32_t off = SWZ((uint32_t)(r * 128 + kp * 4));
            *(uint32_t*)(sm + SM_AH + off) = *reinterpret_cast<uint32_t*>(&hv);
        }
        // ---- stage B (float4 copy of pre-swizzled fp16 image) ----
        {
            const float4* s1 = (const float4*)(wb + ch * 9216);
            float4* d1 = (float4*)(sm + SM_BH);
            for (int i = tid; i < 2304; i += 256) d1[i] = s1[i];
        }
        __syncthreads();
        hmma_chunk(sb, wm, wn, lane, acc);
    }

    hmma_epilogue(acc, row0, wm, wn, lane, bias, Cout, sStat, M, doStat);
    if (doStat) {
        __syncthreads();
        for (int i = tid; i < 2 * HH; i += 256) atomicAdd(&g_stats[i], sStat[i]);
    }
}

// ============================================================================
// Unified GEMM2 (in place): C[M,280] = relu(bn(C)) @ W[280,280] + b
// ============================================================================
__global__ void __launch_bounds__(256, 3)
gemm_inplace_mma(float* __restrict__ C, const uint32_t* __restrict__ wb,
                 const float* __restrict__ bias, int M) {
    extern __shared__ char sm[];
    uint32_t sb = smem_u32(sm);
    const int tid = threadIdx.x, wid = tid >> 5, lane = tid & 31;
    const int wm = wid >> 1, wn = wid & 1;
    const long row0 = (long)blockIdx.x * 64;
    float* sStat = (float*)(sm + SM_STAT);
    float* sSc = (float*)(sm + SM_SC);
    float* sSh = (float*)(sm + SM_SH);

    for (int i = tid; i < 2 * HH; i += 256) sStat[i] = 0.f;
    for (int i = tid; i < HH; i += 256) { sSc[i] = g_scale[i]; sSh[i] = g_shift[i]; }
    float acc[18][4];
#pragma unroll
    for (int nt = 0; nt < 18; nt++)
#pragma unroll
        for (int j = 0; j < 4; j++) acc[nt][j] = 0.f;
    __syncthreads();

    for (int ch = 0; ch < 5; ++ch) {
        if (ch) __syncthreads();
        const int kbase = ch * 64;
        for (int i = tid; i < 2048; i += 256) {
            int r = i >> 5, kp = i & 31;
            int c = kbase + 2 * kp;
            float2 v = make_float2(0.f, 0.f);
            if (c < HH) {
                long row = min(row0 + r, (long)M - 1);
                float2 y = *(const float2*)(C + row * HH + c);
                v.x = fmaxf(fmaf(y.x, sSc[c], sSh[c]), 0.f);
                v.y = fmaxf(fmaf(y.y, sSc[c + 1], sSh[c + 1]), 0.f);
            }
            __half2 hv = __floats2half2_rn(v.x, v.y);
            uint32_t off = SWZ((uint32_t)(r * 128 + kp * 4));
            *(uint32_t*)(sm + SM_AH + off) = *reinterpret_cast<uint32_t*>(&hv);
        }
        {
            const float4* s1 = (const float4*)(wb + ch * 9216);
            float4* d1 = (float4*)(sm + SM_BH);
            for (int i = tid; i < 2304; i += 256) d1[i] = s1[i];
        }
        __syncthreads();
        hmma_chunk(sb, wm, wn, lane, acc);
    }

    hmma_epilogue(acc, row0, wm, wn, lane, bias, C, sStat, M, 1);
    __syncthreads();
    for (int i = tid; i < 2 * HH; i += 256) atomicAdd(&g_stats[i], sStat[i]);
}

// ============================================================================
// Combine: Y[e] = P1[dst[e]] + P2[src[e]] + ea[e]@W1c + bias, fused BN stats.
// ============================================================================
__global__ void __launch_bounds__(256)
combine_msg(const float* __restrict__ P1, const float* __restrict__ P2,
            const float* __restrict__ ea,
            const int* __restrict__ dst, const int* __restrict__ src,
            const float* __restrict__ W1c,   // rows 560..563 of Wm1: [4*HH] linear
            const float* __restrict__ bias, float* __restrict__ Y) {
    __shared__ float sStat[2 * HH];
    __shared__ float sW[EFF * HH];
    __shared__ float sB[HH];
    __shared__ int sD[32], sS[32];
    __shared__ float4 sEv[32];
    const int tid = threadIdx.x;
    const long e0 = (long)blockIdx.x * 32;

    for (int i = tid; i < 2 * HH; i += 256) sStat[i] = 0.f;
    for (int i = tid; i < EFF * HH; i += 256) sW[i] = W1c[i];
    for (int i = tid; i < HH; i += 256) sB[i] = bias[i];
    if (tid < 32) {
        long e = e0 + tid;
        sD[tid] = dst[e];
        sS[tid] = src[e];
        sEv[tid] = *(const float4*)(ea + e * EFF);
    }
    __syncthreads();

    for (int it = tid; it < 32 * 70; it += 256) {
        int er = it / 70, c4 = it - er * 70;
        int c = c4 * 4;
        long e = e0 + er;
        float4 a = *(const float4*)(P1 + (long)sD[er] * HH + c);
        float4 b = *(const float4*)(P2 + (long)sS[er] * HH + c);
        float4 ev = sEv[er];
        float4 v;
        v.x = a.x + b.x + sB[c + 0] + ev.x * sW[c + 0] + ev.y * sW[HH + c + 0] + ev.z * sW[2 * HH + c + 0] + ev.w * sW[3 * HH + c + 0];
        v.y = a.y + b.y + sB[c + 1] + ev.x * sW[c + 1] + ev.y * sW[HH + c + 1] + ev.z * sW[2 * HH + c + 1] + ev.w * sW[3 * HH + c + 1];
        v.z = a.z + b.z + sB[c + 2] + ev.x * sW[c + 2] + ev.y * sW[HH + c + 2] + ev.z * sW[2 * HH + c + 2] + ev.w * sW[3 * HH + c + 2];
        v.w = a.w + b.w + sB[c + 3] + ev.x * sW[c + 3] + ev.y * sW[HH + c + 3] + ev.z * sW[2 * HH + c + 3] + ev.w * sW[3 * HH + c + 3];
        *(float4*)(Y + e * HH + c) = v;
        atomicAdd(&sStat[c + 0], v.x);
        atomicAdd(&sStat[c + 1], v.y);
        atomicAdd(&sStat[c + 2], v.z);
        atomicAdd(&sStat[c + 3], v.w);
        atomicAdd(&sStat[HH + c + 0], v.x * v.x);
        atomicAdd(&sStat[HH + c + 1], v.y * v.y);
        atomicAdd(&sStat[HH + c + 2], v.z * v.z);
        atomicAdd(&sStat[HH + c + 3], v.w * v.w);
    }
    __syncthreads();
    for (int i = tid; i < 2 * HH; i += 256) atomicAdd(&g_stats[i], sStat[i]);
}

// ---------------- finalize BN stats -> scale/shift; self-zero ----------------
__global__ void finalize_stats(const float* __restrict__ g, const float* __restrict__ be,
                               float invM) {
    int c = threadIdx.x;
    if (c >= HH) return;
    float s = g_stats[c];
    float s2 = g_stats[HH + c];
    g_stats[c] = 0.f;
    g_stats[HH + c] = 0.f;
    float mean = s * invM;
    float var = s2 * invM - mean * mean;
    float rstd = rsqrtf(var + 1e-5f);
    float sc = g[c] * rstd;
    g_scale[c] = sc;
    g_shift[c] = fmaf(-mean, sc, be[c]);
}

// ---------------- scatter: agg[dst[e]] += relu(bn(Y[e])) ----------------
__global__ void scatter_bn_relu(const float* __restrict__ Y, const int* __restrict__ dst,
                                float* __restrict__ agg) {
    long i = (long)blockIdx.x * 256 + threadIdx.x;
    if (i >= (long)EE * (HH / 4)) return;
    int e = (int)(i / (HH / 4));
    int c = (int)(i - (long)e * (HH / 4)) * 4;
    float4 y = *reinterpret_cast<const float4*>(Y + (long)e * HH + c);
    float* p = agg + (long)dst[e] * HH + c;
    float v0 = fmaf(y.x, g_scale[c + 0], g_shift[c + 0]);
    float v1 = fmaf(y.y, g_scale[c + 1], g_shift[c + 1]);
    float v2 = fmaf(y.z, g_scale[c + 2], g_shift[c + 2]);
    float v3 = fmaf(y.w, g_scale[c + 3], g_shift[c + 3]);
    if (v0 > 0.f) atomicAdd(p + 0, v0);
    if (v1 > 0.f) atomicAdd(p + 1, v1);
    if (v2 > 0.f) atomicAdd(p + 2, v2);
    if (v3 > 0.f) atomicAdd(p + 3, v3);
}

// ---------------- residual: h += relu(bn(U)) ----------------
__global__ void residual_bn_relu(const float* __restrict__ U, float* __restrict__ h) {
    int i = blockIdx.x * 256 + threadIdx.x;
    if (i >= NN * HH / 4) return;
    int c = (i % (HH / 4)) * 4;
    float4 u = *reinterpret_cast<const float4*>(U + (long)i * 4);
    float4 hv = *reinterpret_cast<float4*>(h + (long)i * 4);
    hv.x += fmaxf(fmaf(u.x, g_scale[c + 0], g_shift[c + 0]), 0.f);
    hv.y += fmaxf(fmaf(u.y, g_scale[c + 1], g_shift[c + 1]), 0.f);
    hv.z += fmaxf(fmaf(u.z, g_scale[c + 2], g_shift[c + 2]), 0.f);
    hv.w += fmaxf(fmaf(u.w, g_scale[c + 3], g_shift[c + 3]), 0.f);
    *reinterpret_cast<float4*>(h + (long)i * 4) = hv;
}

// ---------------- pooling + head ----------------
__global__ void pool_accum(const float* __restrict__ h, const int* __restrict__ batch,
                           float* __restrict__ pool) {
    int i = blockIdx.x * 256 + threadIdx.x;
    if (i >= NN * HH / 4) return;
    int n = i / (HH / 4);
    int c = (i - n * (HH / 4)) * 4;
    float4 v = *reinterpret_cast<const float4*>(h + (long)i * 4);
    float* p = pool + (long)batch[n] * HH + c;
    atomicAdd(p + 0, v.x);
    atomicAdd(p + 1, v.y);
    atomicAdd(p + 2, v.z);
    atomicAdd(p + 3, v.w);
}

__global__ void pool_count(const int* __restrict__ batch, float* __restrict__ cnt) {
    int n = blockIdx.x * 256 + threadIdx.x;
    if (n < NN) atomicAdd(&cnt[batch[n]], 1.0f);
}

__global__ void head_kernel(const float* __restrict__ pool, const float* __restrict__ cnt,
                            const float* __restrict__ Wmu, const float* __restrict__ bmu,
                            float* __restrict__ out) {
    int gph = blockIdx.x;
    int z = threadIdx.x;
    float inv = 1.0f / fmaxf(cnt[gph], 1.0f);
    float s = bmu[z];
    for (int k = 0; k < HH; k++) s = fmaf(pool[gph * HH + k] * inv, Wmu[k * ZZ + z], s);
    out[gph * ZZ + z] = s;
}

// ---------------- host orchestration ----------------
extern "C" void kernel_launch(void* const* d_in, const int* in_sizes, int n_in,
                              void* d_out, int out_size) {
    const float *x, *edge_attr, *Wi, *bi, *Wm1, *bm1, *g1, *be1, *Wm2, *bm2, *g2, *be2;
    const float *Wu1, *bu1, *g3, *be3, *Wu2, *bu2, *g4, *be4, *Wmu, *bmu;
    const int *edge_index, *batch;

    if (in_sizes[2] == 2 * EE) {
        x = (const float*)d_in[0];   edge_attr = (const float*)d_in[1];
        edge_index = (const int*)d_in[2]; batch = (const int*)d_in[3];
        Wi = (const float*)d_in[4];  bi = (const float*)d_in[5];
        Wm1 = (const float*)d_in[6]; bm1 = (const float*)d_in[7];
        g1 = (const float*)d_in[8];  be1 = (const float*)d_in[9];
        Wm2 = (const float*)d_in[10]; bm2 = (const float*)d_in[11];
        g2 = (const float*)d_in[12]; be2 = (const float*)d_in[13];
        Wu1 = (const float*)d_in[14]; bu1 = (const float*)d_in[15];
        g3 = (const float*)d_in[16]; be3 = (const float*)d_in[17];
        Wu2 = (const float*)d_in[18]; bu2 = (const float*)d_in[19];
        g4 = (const float*)d_in[20]; be4 = (const float*)d_in[21];
        Wmu = (const float*)d_in[22]; bmu = (const float*)d_in[23];
    } else {
        x = (const float*)d_in[0];   edge_attr = (const float*)d_in[1];
        Wi = (const float*)d_in[2];  bi = (const float*)d_in[3];
        Wm1 = (const float*)d_in[4]; bm1 = (const float*)d_in[5];
        g1 = (const float*)d_in[6];  be1 = (const float*)d_in[7];
        Wm2 = (const float*)d_in[8]; bm2 = (const float*)d_in[9];
        g2 = (const float*)d_in[10]; be2 = (const float*)d_in[11];
        Wu1 = (const float*)d_in[12]; bu1 = (const float*)d_in[13];
        g3 = (const float*)d_in[14]; be3 = (const float*)d_in[15];
        Wu2 = (const float*)d_in[16]; bu2 = (const float*)d_in[17];
        g4 = (const float*)d_in[18]; be4 = (const float*)d_in[19];
        Wmu = (const float*)d_in[20]; bmu = (const float*)d_in[21];
        edge_index = (const int*)d_in[22]; batch = (const int*)d_in[23];
    }
    const int* src = edge_index;
    const int* dst = edge_index + EE;

    float *hbuf, *Ybuf, *aggbuf, *Ubuf, *poolbuf, *cntbuf, *statsbuf, *zbuf;
    uint32_t *wb;
    cudaGetSymbolAddress((void**)&hbuf, g_h);
    cudaGetSymbolAddress((void**)&Ybuf, g_Y);
    cudaGetSymbolAddress((void**)&aggbuf, g_agg);
    cudaGetSymbolAddress((void**)&Ubuf, g_U);
    cudaGetSymbolAddress((void**)&poolbuf, g_pool);
    cudaGetSymbolAddress((void**)&cntbuf, g_cnt);
    cudaGetSymbolAddress((void**)&statsbuf, g_stats);
    cudaGetSymbolAddress((void**)&zbuf, g_zb);
    cudaGetSymbolAddress((void**)&wb, g_wb);

    cudaFuncSetAttribute(gemm_cat_mma, cudaFuncAttributeMaxDynamicSharedMemorySize, SM_TOT);
    cudaFuncSetAttribute(gemm_inplace_mma, cudaFuncAttributeMaxDynamicSharedMemorySize, SM_TOT);

    const int NH_BLKS = (NN * HH + 255) / 256;
    const int NH4_BLKS = (NN * HH / 4 + 255) / 256;
    const int MSG_BLKS = EE / 64;                     // 5000
    const int UPD_BLKS = (NN + 63) / 64;              // 313
    const long EH4 = (long)EE * (HH / 4);
    const int SC_BLKS = (int)((EH4 + 255) / 256);

    zero4_kernel<<<1, 256>>>((float4*)statsbuf, 2 * HH / 4);
    zero4_kernel<<<1, 256>>>((float4*)zbuf, HH / 4);
    input_layer<<<NH_BLKS, 256>>>(x, Wi, bi, hbuf);

    // ---- pre-convert ALL weight images ----
    for (int l = 0; l < LL; l++) {
        uint32_t* base = wb + (long)l * 29 * 9216;
        const float* wm1 = Wm1 + (long)l * K_MSG * HH;
        conv_w<<<(5 * 9216) / 256, 256>>>(wm1, HH, 5, base);                       // W1a
        conv_w<<<(5 * 9216) / 256, 256>>>(wm1 + 280 * HH, HH, 5, base + 5 * 9216); // W1b
        conv_w<<<(5 * 9216) / 256, 256>>>(Wm2 + (long)l * HH * HH, HH, 5, base + 10 * 9216);
        conv_w<<<(9 * 9216) / 256, 256>>>(Wu1 + (long)l * K_UPD * HH, K_UPD, 9, base + 15 * 9216);
        conv_w<<<(5 * 9216) / 256, 256>>>(Wu2 + (long)l * HH * HH, HH, 5, base + 24 * 9216);
    }

    for (int l = 0; l < LL; l++) {
        uint32_t* wbase = wb + (long)l * 29 * 9216;
        const float* wm1 = Wm1 + (long)l * K_MSG * HH;

        // ---- message MLP layer 1, distributed: P1=h@W1a, P2=h@W1b, combine ----
        gemm_cat_mma<<<UPD_BLKS, 256, SM_TOT>>>(hbuf, nullptr, hbuf, nullptr, nullptr,
                                                wbase, zbuf, Ubuf /*P1*/, NN, HH, 5, 0);
        gemm_cat_mma<<<UPD_BLKS, 256, SM_TOT>>>(hbuf, nullptr, hbuf, nullptr, nullptr,
                                                wbase + 5 * 9216, zbuf, aggbuf /*P2*/, NN, HH, 5, 0);
        combine_msg<<<EE / 32, 256>>>(Ubuf, aggbuf, edge_attr, dst, src,
                                      wm1 + 560 * HH, bm1 + l * HH, Ybuf);
        finalize_stats<<<1, 288>>>(g1 + l * HH, be1 + l * HH, 1.0f / EE);
        gemm_inplace_mma<<<MSG_BLKS, 256, SM_TOT>>>(Ybuf, wbase + 10 * 9216, bm2 + l * HH, EE);
        finalize_stats<<<1, 288>>>(g2 + l * HH, be2 + l * HH, 1.0f / EE);

        // ---- aggregate ----
        zero4_kernel<<<NH4_BLKS, 256>>>((float4*)aggbuf, NN * HH / 4);
        scatter_bn_relu<<<SC_BLKS, 256>>>(Ybuf, dst, aggbuf);

        // ---- update MLP on nodes ----
        gemm_cat_mma<<<UPD_BLKS, 256, SM_TOT>>>(hbuf, nullptr, aggbuf, nullptr, nullptr,
                                                wbase + 15 * 9216, bu1 + l * HH, Ubuf, NN, K_UPD, 9, 1);
        finalize_stats<<<1, 288>>>(g3 + l * HH, be3 + l * HH, 1.0f / NN);
        gemm_inplace_mma<<<UPD_BLKS, 256, SM_TOT>>>(Ubuf, wbase + 24 * 9216, bu2 + l * HH, NN);
        finalize_stats<<<1, 288>>>(g4 + l * HH, be4 + l * HH, 1.0f / NN);
        residual_bn_relu<<<NH4_BLKS, 256>>>(Ubuf, hbuf);
    }

    zero4_kernel<<<(GG * HH / 4 + 255) / 256, 256>>>((float4*)poolbuf, GG * HH / 4);
    zero4_kernel<<<1, 256>>>((float4*)cntbuf, GG / 4);
    pool_accum<<<NH4_BLKS, 256>>>(hbuf, batch, poolbuf);
    pool_count<<<(NN + 255) / 256, 256>>>(batch, cntbuf);
    head_kernel<<<GG, ZZ>>>(poolbuf, cntbuf, Wmu, bmu, (float*)d_out);
}